// round 2
// baseline (speedup 1.0000x reference)
#include <cuda_runtime.h>
#include <cuda_bf16.h>
#include <cstdint>

// Problem constants
#define BATCH   4
#define SEQ     2048
#define DIM     768
#define HEADS   12
#define HDIM    64
#define M_TOT   (BATCH * SEQ)          // 8192
#define QKV_N   (3 * DIM)              // 2304

// Scratch (device globals: allocation-guard-safe)
__device__ float g_qkv[(size_t)M_TOT * QKV_N];   // [B*N, 2304]
__device__ float g_att[(size_t)M_TOT * DIM];     // [B*N, 768]  (b,n,h,d) packed

// ---------------------------------------------------------------------------
// SGEMM: C[M,N] = A[M,K] @ B[K,N] (+ bias[N] if bias != nullptr)
// 128x128 block tile, BK=8, 256 threads, 8x8 per-thread microtile.
// Assumes M%128==0, N%128==0, K%8==0 (true for all shapes here).
// ---------------------------------------------------------------------------
__global__ __launch_bounds__(256)
void sgemm128(const float* __restrict__ A, const float* __restrict__ B,
              const float* __restrict__ bias, float* __restrict__ C,
              int M, int N, int K)
{
    __shared__ __align__(16) float As[8][128];
    __shared__ __align__(16) float Bs[8][132];

    const int bx = blockIdx.x;            // N tile
    const int by = blockIdx.y;            // M tile
    const int tid = threadIdx.x;
    const int tx = tid & 15;              // 0..15  (N micro)
    const int ty = tid >> 4;              // 0..15  (M micro)

    // global load mapping
    const int arow = tid >> 1;            // 0..127
    const int acol = (tid & 1) * 4;       // 0 or 4
    const int brow = tid >> 5;            // 0..7
    const int bcol = (tid & 31) * 4;      // 0..124

    const float* Ag = A + (size_t)(by * 128 + arow) * K + acol;
    const float* Bg = B + (size_t)brow * N + bx * 128 + bcol;

    float acc[8][8];
    #pragma unroll
    for (int i = 0; i < 8; i++)
        #pragma unroll
        for (int j = 0; j < 8; j++) acc[i][j] = 0.f;

    for (int k0 = 0; k0 < K; k0 += 8) {
        float4 av = *(const float4*)Ag;
        float4 bv = *(const float4*)Bg;
        Ag += 8;
        Bg += (size_t)8 * N;

        // store A transposed: As[k][m]
        As[acol + 0][arow] = av.x;
        As[acol + 1][arow] = av.y;
        As[acol + 2][arow] = av.z;
        As[acol + 3][arow] = av.w;
        *(float4*)&Bs[brow][bcol] = bv;
        __syncthreads();

        #pragma unroll
        for (int kk = 0; kk < 8; kk++) {
            float4 a0 = *(const float4*)&As[kk][ty * 8];
            float4 a1 = *(const float4*)&As[kk][ty * 8 + 4];
            float4 b0 = *(const float4*)&Bs[kk][tx * 8];
            float4 b1 = *(const float4*)&Bs[kk][tx * 8 + 4];
            float ar[8] = {a0.x, a0.y, a0.z, a0.w, a1.x, a1.y, a1.z, a1.w};
            float br[8] = {b0.x, b0.y, b0.z, b0.w, b1.x, b1.y, b1.z, b1.w};
            #pragma unroll
            for (int i = 0; i < 8; i++)
                #pragma unroll
                for (int j = 0; j < 8; j++)
                    acc[i][j] += ar[i] * br[j];
        }
        __syncthreads();
    }

    // epilogue
    float bb[8];
    #pragma unroll
    for (int j = 0; j < 8; j++)
        bb[j] = bias ? bias[bx * 128 + tx * 8 + j] : 0.f;

    #pragma unroll
    for (int i = 0; i < 8; i++) {
        float* cp = C + (size_t)(by * 128 + ty * 8 + i) * N + bx * 128 + tx * 8;
        float4 v0 = make_float4(acc[i][0] + bb[0], acc[i][1] + bb[1],
                                acc[i][2] + bb[2], acc[i][3] + bb[3]);
        float4 v1 = make_float4(acc[i][4] + bb[4], acc[i][5] + bb[5],
                                acc[i][6] + bb[6], acc[i][7] + bb[7]);
        *(float4*)cp = v0;
        *(float4*)(cp + 4) = v1;
    }
}

// ---------------------------------------------------------------------------
// Flash attention, fp32. One thread = one q row. Block = 128 q rows.
// Grid: (SEQ/128, HEADS, BATCH). K/V staged in smem, 32 rows per tile.
// qkv layout: [B*N, 2304] with q at +h*64, k at +768+h*64, v at +1536+h*64
// ---------------------------------------------------------------------------
__global__ __launch_bounds__(128)
void attn_kernel(const float* __restrict__ qkv, float* __restrict__ out)
{
    const int b  = blockIdx.z;
    const int h  = blockIdx.y;
    const int nq = blockIdx.x * 128 + threadIdx.x;
    const int tid = threadIdx.x;
    const float scale = 0.125f;  // 1/sqrt(64)

    __shared__ __align__(16) float Ks[32][64];
    __shared__ __align__(16) float Vs[32][64];

    // load this thread's q row into registers
    float q[64];
    {
        const float* qp = qkv + (size_t)(b * SEQ + nq) * QKV_N + h * HDIM;
        #pragma unroll
        for (int d = 0; d < 64; d += 4) {
            float4 t = *(const float4*)(qp + d);
            q[d] = t.x; q[d + 1] = t.y; q[d + 2] = t.z; q[d + 3] = t.w;
        }
    }

    float acc[64];
    #pragma unroll
    for (int d = 0; d < 64; d++) acc[d] = 0.f;
    float m = -1e30f, l = 0.f;

    for (int kt = 0; kt < SEQ / 32; kt++) {
        // cooperative tile load: 32 rows x 64 cols, float4 granularity
        for (int f = tid; f < 512; f += 128) {
            int r = f >> 4;
            int c = (f & 15) << 2;
            const float* base = qkv + (size_t)(b * SEQ + kt * 32 + r) * QKV_N + h * HDIM + c;
            *(float4*)&Ks[r][c] = *(const float4*)(base + DIM);       // K
            *(float4*)&Vs[r][c] = *(const float4*)(base + 2 * DIM);   // V
        }
        __syncthreads();

        float s[32];
        float tmax = -1e30f;
        #pragma unroll
        for (int j = 0; j < 32; j += 2) {
            float sum0 = 0.f, sum1 = 0.f;
            const float* __restrict__ k0 = &Ks[j][0];
            const float* __restrict__ k1 = &Ks[j + 1][0];
            #pragma unroll
            for (int d = 0; d < 64; d++) {
                sum0 += q[d] * k0[d];
                sum1 += q[d] * k1[d];
            }
            s[j]     = sum0 * scale;
            s[j + 1] = sum1 * scale;
            tmax = fmaxf(tmax, fmaxf(s[j], s[j + 1]));
        }

        float mn = fmaxf(m, tmax);
        float corr = __expf(m - mn);
        l *= corr;
        #pragma unroll
        for (int d = 0; d < 64; d++) acc[d] *= corr;

        #pragma unroll
        for (int j = 0; j < 32; j++) {
            float p = __expf(s[j] - mn);
            l += p;
            const float* __restrict__ vr = &Vs[j][0];
            #pragma unroll
            for (int d = 0; d < 64; d++) acc[d] += p * vr[d];
        }
        m = mn;
        __syncthreads();
    }

    const float inv = 1.f / l;
    float* op = out + (size_t)(b * SEQ + nq) * DIM + h * HDIM;
    #pragma unroll
    for (int d = 0; d < 64; d += 4) {
        float4 t = make_float4(acc[d] * inv, acc[d + 1] * inv,
                               acc[d + 2] * inv, acc[d + 3] * inv);
        *(float4*)(op + d) = t;
    }
}

// ---------------------------------------------------------------------------
extern "C" void kernel_launch(void* const* d_in, const int* in_sizes, int n_in,
                              void* d_out, int out_size)
{
    const float* x      = (const float*)d_in[0];
    const float* w_qkv  = (const float*)d_in[1];
    const float* w_proj = (const float*)d_in[2];
    const float* b_proj = (const float*)d_in[3];
    float* out = (float*)d_out;

    float* qkv = nullptr;
    float* att = nullptr;
    cudaGetSymbolAddress((void**)&qkv, g_qkv);
    cudaGetSymbolAddress((void**)&att, g_att);

    // 1) qkv = x @ w_qkv           [8192,768] @ [768,2304]
    sgemm128<<<dim3(QKV_N / 128, M_TOT / 128), 256>>>(x, w_qkv, nullptr, qkv,
                                                      M_TOT, QKV_N, DIM);
    // 2) attention -> att          [8192,768]
    attn_kernel<<<dim3(SEQ / 128, HEADS, BATCH), 128>>>(qkv, att);
    // 3) out = att @ w_proj + b    [8192,768] @ [768,768]
    sgemm128<<<dim3(DIM / 128, M_TOT / 128), 256>>>(att, w_proj, b_proj, out,
                                                    M_TOT, DIM, DIM);
}

// round 3
// speedup vs baseline: 2.3489x; 2.3489x over previous
#include <cuda_runtime.h>
#include <cstdint>

#define BATCH   4
#define SEQ     2048
#define DIM     768
#define HEADS   12
#define HDIM    64
#define M_TOT   8192
#define QKV_N   2304

// Scratch (device globals: allocation-guard-safe)
__device__ float g_qkv[(size_t)M_TOT * QKV_N];   // [B*N, 2304]
__device__ float g_att[(size_t)M_TOT * DIM];     // [B*N, 768]

// ---------------------------------------------------------------------------
// tf32 helpers
// ---------------------------------------------------------------------------
__device__ __forceinline__ uint32_t f2tf(float x) {
    uint32_t u;
    asm("cvt.rna.tf32.f32 %0, %1;" : "=r"(u) : "f"(x));
    return u;
}

__device__ __forceinline__ void mma8(float* c,
                                     uint32_t a0, uint32_t a1, uint32_t a2, uint32_t a3,
                                     uint32_t b0, uint32_t b1) {
    asm volatile(
        "mma.sync.aligned.m16n8k8.row.col.f32.tf32.tf32.f32 "
        "{%0,%1,%2,%3},{%4,%5,%6,%7},{%8,%9},{%0,%1,%2,%3};"
        : "+f"(c[0]), "+f"(c[1]), "+f"(c[2]), "+f"(c[3])
        : "r"(a0), "r"(a1), "r"(a2), "r"(a3), "r"(b0), "r"(b1));
}

// ---------------------------------------------------------------------------
// 3xTF32 GEMM: C[M,N] = A[M,K] @ B[K,N] (+bias). BM=128 BN=128 BK=16.
// 256 threads = 8 warps (4 warp_m x 2 warp_n), warp tile 32x64.
// smem K-major with ld=136 -> conflict-free fragment loads.
// ---------------------------------------------------------------------------
#define LDT 136
__global__ __launch_bounds__(256, 2)
void gemm_tf32(const float* __restrict__ A, const float* __restrict__ B,
               const float* __restrict__ bias, float* __restrict__ C,
               int N, int K)
{
    __shared__ uint32_t Ah[16 * LDT], Al[16 * LDT];
    __shared__ uint32_t Bh[16 * LDT], Bl[16 * LDT];

    const int tid  = threadIdx.x;
    const int lane = tid & 31;
    const int wid  = tid >> 5;
    const int wm   = wid >> 1;          // 0..3
    const int wn   = wid & 1;           // 0..1
    const int r0   = lane >> 2;         // groupID
    const int c0   = lane & 3;          // threadID_in_group
    const int bx   = blockIdx.x;
    const int by   = blockIdx.y;

    float acc[2][8][4];
    #pragma unroll
    for (int mi = 0; mi < 2; mi++)
        #pragma unroll
        for (int ni = 0; ni < 8; ni++)
            #pragma unroll
            for (int j = 0; j < 4; j++) acc[mi][ni][j] = 0.f;

    for (int k0 = 0; k0 < K; k0 += 16) {
        // ---- load tiles to smem (split hi/lo) ----
        #pragma unroll
        for (int i = 0; i < 2; i++) {
            int idx = tid + i * 256;
            // A: 128 rows x 16 cols
            int ar = idx >> 2, ac4 = (idx & 3) * 4;
            float4 av = *(const float4*)(A + (size_t)(by * 128 + ar) * K + k0 + ac4);
            float aj[4] = {av.x, av.y, av.z, av.w};
            #pragma unroll
            for (int j = 0; j < 4; j++) {
                uint32_t hi = f2tf(aj[j]);
                uint32_t lo = f2tf(aj[j] - __uint_as_float(hi));
                Ah[(ac4 + j) * LDT + ar] = hi;
                Al[(ac4 + j) * LDT + ar] = lo;
            }
            // B: 16 rows x 128 cols
            int bk = idx >> 5, bc4 = (idx & 31) * 4;
            float4 bv = *(const float4*)(B + (size_t)(k0 + bk) * N + bx * 128 + bc4);
            float bj[4] = {bv.x, bv.y, bv.z, bv.w};
            #pragma unroll
            for (int j = 0; j < 4; j++) {
                uint32_t hi = f2tf(bj[j]);
                uint32_t lo = f2tf(bj[j] - __uint_as_float(hi));
                Bh[bk * LDT + bc4 + j] = hi;
                Bl[bk * LDT + bc4 + j] = lo;
            }
        }
        __syncthreads();

        #pragma unroll
        for (int ks = 0; ks < 2; ks++) {
            const int kb = ks * 8;
            uint32_t ah[2][4], al[2][4];
            #pragma unroll
            for (int mi = 0; mi < 2; mi++) {
                int m = wm * 32 + mi * 16 + r0;
                int k = kb + c0;
                ah[mi][0] = Ah[k * LDT + m];
                ah[mi][1] = Ah[k * LDT + m + 8];
                ah[mi][2] = Ah[(k + 4) * LDT + m];
                ah[mi][3] = Ah[(k + 4) * LDT + m + 8];
                al[mi][0] = Al[k * LDT + m];
                al[mi][1] = Al[k * LDT + m + 8];
                al[mi][2] = Al[(k + 4) * LDT + m];
                al[mi][3] = Al[(k + 4) * LDT + m + 8];
            }
            #pragma unroll
            for (int ni = 0; ni < 8; ni++) {
                int n = wn * 64 + ni * 8 + r0;
                int k = kb + c0;
                uint32_t bh0 = Bh[k * LDT + n];
                uint32_t bh1 = Bh[(k + 4) * LDT + n];
                uint32_t bl0 = Bl[k * LDT + n];
                uint32_t bl1 = Bl[(k + 4) * LDT + n];
                #pragma unroll
                for (int mi = 0; mi < 2; mi++) {
                    mma8(acc[mi][ni], ah[mi][0], ah[mi][1], ah[mi][2], ah[mi][3], bh0, bh1);
                    mma8(acc[mi][ni], ah[mi][0], ah[mi][1], ah[mi][2], ah[mi][3], bl0, bl1);
                    mma8(acc[mi][ni], al[mi][0], al[mi][1], al[mi][2], al[mi][3], bh0, bh1);
                }
            }
        }
        __syncthreads();
    }

    // ---- epilogue ----
    #pragma unroll
    for (int mi = 0; mi < 2; mi++) {
        int r = by * 128 + wm * 32 + mi * 16 + r0;
        #pragma unroll
        for (int ni = 0; ni < 8; ni++) {
            int cc = bx * 128 + wn * 64 + ni * 8 + c0 * 2;
            float bb0 = bias ? bias[cc] : 0.f;
            float bb1 = bias ? bias[cc + 1] : 0.f;
            *(float2*)(C + (size_t)r * N + cc) =
                make_float2(acc[mi][ni][0] + bb0, acc[mi][ni][1] + bb1);
            *(float2*)(C + (size_t)(r + 8) * N + cc) =
                make_float2(acc[mi][ni][2] + bb0, acc[mi][ni][3] + bb1);
        }
    }
}

// ---------------------------------------------------------------------------
// tf32 flash attention. 256 threads = 8 warps; warp owns 16 q rows (Br=128).
// KV tile Bc=64, hd=64. Grid: (SEQ/128, HEADS, BATCH).
// Dynamic smem: Ks[64][76] + Vs[64][72] + Ps[128][68] (tf32 bits) = 72704 B.
// ---------------------------------------------------------------------------
#define LDK 76
#define LDV 72
#define LDP 68
#define ATTN_SMEM ((64 * LDK + 64 * LDV + 128 * LDP) * 4)

__global__ __launch_bounds__(256, 2)
void attn_tf32(const float* __restrict__ qkv, float* __restrict__ out)
{
    extern __shared__ uint32_t sm[];
    uint32_t* Ks = sm;
    uint32_t* Vs = sm + 64 * LDK;
    uint32_t* Ps = sm + 64 * LDK + 64 * LDV;

    const int tid  = threadIdx.x;
    const int lane = tid & 31;
    const int wid  = tid >> 5;
    const int b    = blockIdx.z;
    const int h    = blockIdx.y;
    const int qbase = blockIdx.x * 128 + wid * 16;
    const int r0 = lane >> 2;
    const int c0 = lane & 3;
    uint32_t* Pw = Ps + wid * 16 * LDP;

    // Q fragments for all 8 k-steps (d = 0..63), pre-scaled by 1/8 (exact pow2)
    uint32_t qa[8][4];
    {
        const float* qp = qkv + (size_t)(b * SEQ + qbase) * QKV_N + h * HDIM;
        #pragma unroll
        for (int ks = 0; ks < 8; ks++) {
            int d = ks * 8 + c0;
            qa[ks][0] = f2tf(0.125f * qp[(size_t)r0 * QKV_N + d]);
            qa[ks][1] = f2tf(0.125f * qp[(size_t)(r0 + 8) * QKV_N + d]);
            qa[ks][2] = f2tf(0.125f * qp[(size_t)r0 * QKV_N + d + 4]);
            qa[ks][3] = f2tf(0.125f * qp[(size_t)(r0 + 8) * QKV_N + d + 4]);
        }
    }

    float o[8][4];
    #pragma unroll
    for (int ni = 0; ni < 8; ni++)
        #pragma unroll
        for (int j = 0; j < 4; j++) o[ni][j] = 0.f;
    float m0 = -1e30f, m1 = -1e30f, l0 = 0.f, l1 = 0.f;

    for (int kt = 0; kt < SEQ / 64; kt++) {
        __syncthreads();
        // cooperative K/V tile load (64 rows x 64 cols each), cvt to tf32
        #pragma unroll
        for (int i = 0; i < 4; i++) {
            int idx = tid + i * 256;
            int row = idx >> 4, c4 = (idx & 15) * 4;
            const float* base = qkv + (size_t)(b * SEQ + kt * 64 + row) * QKV_N + h * HDIM + c4;
            float4 kv = *(const float4*)(base + DIM);
            float4 vv = *(const float4*)(base + 2 * DIM);
            uint4 ku = make_uint4(f2tf(kv.x), f2tf(kv.y), f2tf(kv.z), f2tf(kv.w));
            uint4 vu = make_uint4(f2tf(vv.x), f2tf(vv.y), f2tf(vv.z), f2tf(vv.w));
            *(uint4*)&Ks[row * LDK + c4] = ku;
            *(uint4*)&Vs[row * LDV + c4] = vu;
        }
        __syncthreads();

        // S = Q K^T  (16 x 64 per warp)
        float s[8][4];
        #pragma unroll
        for (int ni = 0; ni < 8; ni++)
            #pragma unroll
            for (int j = 0; j < 4; j++) s[ni][j] = 0.f;

        #pragma unroll
        for (int ks = 0; ks < 8; ks++) {
            int d = ks * 8 + c0;
            #pragma unroll
            for (int ni = 0; ni < 8; ni++) {
                int kvr = ni * 8 + r0;
                uint32_t b0 = Ks[kvr * LDK + d];
                uint32_t b1 = Ks[kvr * LDK + d + 4];
                mma8(s[ni], qa[ks][0], qa[ks][1], qa[ks][2], qa[ks][3], b0, b1);
            }
        }

        // online softmax (rows r0 and r0+8)
        float tm0 = -1e30f, tm1 = -1e30f;
        #pragma unroll
        for (int ni = 0; ni < 8; ni++) {
            tm0 = fmaxf(tm0, fmaxf(s[ni][0], s[ni][1]));
            tm1 = fmaxf(tm1, fmaxf(s[ni][2], s[ni][3]));
        }
        tm0 = fmaxf(tm0, __shfl_xor_sync(0xffffffffu, tm0, 1));
        tm0 = fmaxf(tm0, __shfl_xor_sync(0xffffffffu, tm0, 2));
        tm1 = fmaxf(tm1, __shfl_xor_sync(0xffffffffu, tm1, 1));
        tm1 = fmaxf(tm1, __shfl_xor_sync(0xffffffffu, tm1, 2));

        float nm0 = fmaxf(m0, tm0), nm1 = fmaxf(m1, tm1);
        float cor0 = __expf(m0 - nm0), cor1 = __expf(m1 - nm1);
        m0 = nm0; m1 = nm1;
        l0 *= cor0; l1 *= cor1;
        #pragma unroll
        for (int ni = 0; ni < 8; ni++) {
            o[ni][0] *= cor0; o[ni][1] *= cor0;
            o[ni][2] *= cor1; o[ni][3] *= cor1;
        }

        __syncwarp();
        #pragma unroll
        for (int ni = 0; ni < 8; ni++) {
            float p0 = __expf(s[ni][0] - nm0);
            float p1 = __expf(s[ni][1] - nm0);
            float p2 = __expf(s[ni][2] - nm1);
            float p3 = __expf(s[ni][3] - nm1);
            l0 += p0 + p1;
            l1 += p2 + p3;
            int col = ni * 8 + c0 * 2;
            *(uint2*)&Pw[r0 * LDP + col]       = make_uint2(f2tf(p0), f2tf(p1));
            *(uint2*)&Pw[(r0 + 8) * LDP + col] = make_uint2(f2tf(p2), f2tf(p3));
        }
        __syncwarp();

        // O += P V   (16 x 64 per warp)
        #pragma unroll
        for (int ks = 0; ks < 8; ks++) {
            int kvl = ks * 8;
            uint32_t a0 = Pw[r0 * LDP + kvl + c0];
            uint32_t a1 = Pw[(r0 + 8) * LDP + kvl + c0];
            uint32_t a2 = Pw[r0 * LDP + kvl + c0 + 4];
            uint32_t a3 = Pw[(r0 + 8) * LDP + kvl + c0 + 4];
            #pragma unroll
            for (int ni = 0; ni < 8; ni++) {
                int d = ni * 8 + r0;
                uint32_t b0 = Vs[(kvl + c0) * LDV + d];
                uint32_t b1 = Vs[(kvl + c0 + 4) * LDV + d];
                mma8(o[ni], a0, a1, a2, a3, b0, b1);
            }
        }
    }

    // finalize
    l0 += __shfl_xor_sync(0xffffffffu, l0, 1);
    l0 += __shfl_xor_sync(0xffffffffu, l0, 2);
    l1 += __shfl_xor_sync(0xffffffffu, l1, 1);
    l1 += __shfl_xor_sync(0xffffffffu, l1, 2);
    float inv0 = 1.f / l0, inv1 = 1.f / l1;

    float* op = out + (size_t)(b * SEQ + qbase) * DIM + h * HDIM;
    #pragma unroll
    for (int ni = 0; ni < 8; ni++) {
        int d = ni * 8 + c0 * 2;
        *(float2*)&op[(size_t)r0 * DIM + d] =
            make_float2(o[ni][0] * inv0, o[ni][1] * inv0);
        *(float2*)&op[(size_t)(r0 + 8) * DIM + d] =
            make_float2(o[ni][2] * inv1, o[ni][3] * inv1);
    }
}

// ---------------------------------------------------------------------------
extern "C" void kernel_launch(void* const* d_in, const int* in_sizes, int n_in,
                              void* d_out, int out_size)
{
    const float* x      = (const float*)d_in[0];
    const float* w_qkv  = (const float*)d_in[1];
    const float* w_proj = (const float*)d_in[2];
    const float* b_proj = (const float*)d_in[3];
    float* out = (float*)d_out;

    float* qkv = nullptr;
    float* att = nullptr;
    cudaGetSymbolAddress((void**)&qkv, g_qkv);
    cudaGetSymbolAddress((void**)&att, g_att);

    cudaFuncSetAttribute(attn_tf32, cudaFuncAttributeMaxDynamicSharedMemorySize, ATTN_SMEM);

    // 1) qkv = x @ w_qkv           [8192,768] @ [768,2304]
    gemm_tf32<<<dim3(QKV_N / 128, M_TOT / 128), 256>>>(x, w_qkv, nullptr, qkv, QKV_N, DIM);
    // 2) attention -> att          [8192,768]
    attn_tf32<<<dim3(SEQ / 128, HEADS, BATCH), 256, ATTN_SMEM>>>(qkv, att);
    // 3) out = att @ w_proj + b    [8192,768] @ [768,768]
    gemm_tf32<<<dim3(DIM / 128, M_TOT / 128), 256>>>(att, w_proj, b_proj, out, DIM, DIM);
}

// round 5
// speedup vs baseline: 2.5454x; 1.0836x over previous
#include <cuda_runtime.h>
#include <cstdint>

#define BATCH   4
#define SEQ     2048
#define DIM     768
#define HEADS   12
#define HDIM    64
#define M_TOT   8192
#define QKV_N   2304

__device__ float g_qkv[(size_t)M_TOT * QKV_N];   // [B*N, 2304]
__device__ float g_att[(size_t)M_TOT * DIM];     // [B*N, 768]

// ---------------------------------------------------------------------------
// helpers
// ---------------------------------------------------------------------------
__device__ __forceinline__ uint32_t f2tf(float x) {
    uint32_t u;
    asm("cvt.rna.tf32.f32 %0, %1;" : "=r"(u) : "f"(x));
    return u;
}

__device__ __forceinline__ void mma8(float* c,
                                     uint32_t a0, uint32_t a1, uint32_t a2, uint32_t a3,
                                     uint32_t b0, uint32_t b1) {
    asm volatile(
        "mma.sync.aligned.m16n8k8.row.col.f32.tf32.tf32.f32 "
        "{%0,%1,%2,%3},{%4,%5,%6,%7},{%8,%9},{%0,%1,%2,%3};"
        : "+f"(c[0]), "+f"(c[1]), "+f"(c[2]), "+f"(c[3])
        : "r"(a0), "r"(a1), "r"(a2), "r"(a3), "r"(b0), "r"(b1));
}

__device__ __forceinline__ void cpa16(void* dst, const void* src) {
    uint32_t d = (uint32_t)__cvta_generic_to_shared(dst);
    asm volatile("cp.async.cg.shared.global [%0], [%1], 16;\n" :: "r"(d), "l"(src));
}
#define CPA_COMMIT()  asm volatile("cp.async.commit_group;\n" ::)
#define CPA_WAIT(n)   asm volatile("cp.async.wait_group %0;\n" :: "n"(n))

// ---------------------------------------------------------------------------
// 3xTF32 GEMM, 3-stage cp.async pipeline. BM=128 BN=128 BK=16, 256 thr.
// A smem m-major (ld=20), B smem n-major (ld=136), raw floats; hi/lo split
// done at fragment-load time.
// ---------------------------------------------------------------------------
#define LDA 20
#define LDB 136
#define A_STG (128 * LDA)
#define B_STG (16 * LDB)
#define GEMM_SMEM ((3 * (A_STG + B_STG)) * 4)

__global__ __launch_bounds__(256, 2)
void gemm_tf32(const float* __restrict__ A, const float* __restrict__ B,
               const float* __restrict__ bias, float* __restrict__ C,
               int N, int K)
{
    extern __shared__ float gsm[];
    float* Asm = gsm;                 // 3 stages of A
    float* Bsm = gsm + 3 * A_STG;     // 3 stages of B

    const int tid  = threadIdx.x;
    const int lane = tid & 31;
    const int wid  = tid >> 5;
    const int wm   = wid >> 1;          // 0..3
    const int wn   = wid & 1;           // 0..1
    const int r0   = lane >> 2;
    const int c0   = lane & 3;
    const int bx   = blockIdx.x;
    const int by   = blockIdx.y;
    const int nt   = K / 16;

    auto prefetch = [&](int t, int s) {
        float* As = Asm + s * A_STG;
        float* Bs = Bsm + s * B_STG;
        #pragma unroll
        for (int i = 0; i < 2; i++) {
            int idx = tid + i * 256;
            int ar = idx >> 2, ac4 = (idx & 3) * 4;
            cpa16(As + ar * LDA + ac4,
                  A + (size_t)(by * 128 + ar) * K + t * 16 + ac4);
            int bk = idx >> 5, bc4 = (idx & 31) * 4;
            cpa16(Bs + bk * LDB + bc4,
                  B + (size_t)(t * 16 + bk) * N + bx * 128 + bc4);
        }
    };

    float acc[2][8][4];
    #pragma unroll
    for (int mi = 0; mi < 2; mi++)
        #pragma unroll
        for (int ni = 0; ni < 8; ni++)
            #pragma unroll
            for (int j = 0; j < 4; j++) acc[mi][ni][j] = 0.f;

    prefetch(0, 0); CPA_COMMIT();
    prefetch(1, 1); CPA_COMMIT();

    for (int it = 0; it < nt; it++) {
        CPA_WAIT(1);
        __syncthreads();
        if (it + 2 < nt) prefetch(it + 2, (it + 2) % 3);
        CPA_COMMIT();

        const float* As = Asm + (it % 3) * A_STG;
        const float* Bs = Bsm + (it % 3) * B_STG;

        #pragma unroll
        for (int ks = 0; ks < 2; ks++) {
            const int k = ks * 8 + c0;
            uint32_t ah[2][4], al[2][4];
            #pragma unroll
            for (int mi = 0; mi < 2; mi++) {
                int m = wm * 32 + mi * 16 + r0;
                float f0 = As[m * LDA + k];
                float f1 = As[(m + 8) * LDA + k];
                float f2 = As[m * LDA + k + 4];
                float f3 = As[(m + 8) * LDA + k + 4];
                ah[mi][0] = f2tf(f0); al[mi][0] = f2tf(f0 - __uint_as_float(ah[mi][0]));
                ah[mi][1] = f2tf(f1); al[mi][1] = f2tf(f1 - __uint_as_float(ah[mi][1]));
                ah[mi][2] = f2tf(f2); al[mi][2] = f2tf(f2 - __uint_as_float(ah[mi][2]));
                ah[mi][3] = f2tf(f3); al[mi][3] = f2tf(f3 - __uint_as_float(ah[mi][3]));
            }
            #pragma unroll
            for (int ni = 0; ni < 8; ni++) {
                int n = wn * 64 + ni * 8 + r0;
                float fb0 = Bs[k * LDB + n];
                float fb1 = Bs[(k + 4) * LDB + n];
                uint32_t bh0 = f2tf(fb0), bl0 = f2tf(fb0 - __uint_as_float(bh0));
                uint32_t bh1 = f2tf(fb1), bl1 = f2tf(fb1 - __uint_as_float(bh1));
                #pragma unroll
                for (int mi = 0; mi < 2; mi++) {
                    mma8(acc[mi][ni], ah[mi][0], ah[mi][1], ah[mi][2], ah[mi][3], bh0, bh1);
                    mma8(acc[mi][ni], ah[mi][0], ah[mi][1], ah[mi][2], ah[mi][3], bl0, bl1);
                    mma8(acc[mi][ni], al[mi][0], al[mi][1], al[mi][2], al[mi][3], bh0, bh1);
                }
            }
        }
        __syncthreads();
    }

    // epilogue
    #pragma unroll
    for (int mi = 0; mi < 2; mi++) {
        int r = by * 128 + wm * 32 + mi * 16 + r0;
        #pragma unroll
        for (int ni = 0; ni < 8; ni++) {
            int cc = bx * 128 + wn * 64 + ni * 8 + c0 * 2;
            float bb0 = bias ? bias[cc] : 0.f;
            float bb1 = bias ? bias[cc + 1] : 0.f;
            *(float2*)(C + (size_t)r * N + cc) =
                make_float2(acc[mi][ni][0] + bb0, acc[mi][ni][1] + bb1);
            *(float2*)(C + (size_t)(r + 8) * N + cc) =
                make_float2(acc[mi][ni][2] + bb0, acc[mi][ni][3] + bb1);
        }
    }
}

// ---------------------------------------------------------------------------
// tf32 flash attention with cp.async K/V prefetch overlap.
// 256 thr = 8 warps, warp owns 16 q rows (Br=128), Bc=64, hd=64.
// Raw staging Kr/Vr[64][68] (floats) <- cp.async; convert pass -> Ks/Vs tf32.
// ---------------------------------------------------------------------------
#define LDR 68
#define LDK 76
#define LDV 72
#define LDP 68
#define ATTN_SMEM ((2 * 64 * LDR + 64 * LDK + 64 * LDV + 128 * LDP) * 4)

__global__ __launch_bounds__(256, 2)
void attn_tf32(const float* __restrict__ qkv, float* __restrict__ out)
{
    extern __shared__ float smf[];
    float* Kr = smf;                       // raw K staging
    float* Vr = smf + 64 * LDR;            // raw V staging
    uint32_t* Ks = (uint32_t*)(smf + 2 * 64 * LDR);
    uint32_t* Vs = Ks + 64 * LDK;
    uint32_t* Ps = Vs + 64 * LDV;

    const int tid  = threadIdx.x;
    const int lane = tid & 31;
    const int wid  = tid >> 5;
    const int b    = blockIdx.z;
    const int h    = blockIdx.y;
    const int qbase = blockIdx.x * 128 + wid * 16;
    const int r0 = lane >> 2;
    const int c0 = lane & 3;
    uint32_t* Pw = Ps + wid * 16 * LDP;

    // issue cp.async for KV tile `kt` into raw staging (full 64x64 K and V)
    auto stage_kv = [&](int kt) {
        #pragma unroll
        for (int i = 0; i < 4; i++) {
            int idx = tid + i * 256;          // 0..1023
            int row = idx >> 4;               // 0..63
            int c4  = (idx & 15) * 4;         // 0..60
            const float* base = qkv + (size_t)(b * SEQ + kt * 64 + row) * QKV_N
                                + h * HDIM + c4;
            cpa16(Kr + row * LDR + c4, base + DIM);
            cpa16(Vr + row * LDR + c4, base + 2 * DIM);
        }
    };
    // convert raw staging -> tf32 Ks/Vs
    auto convert_kv = [&]() {
        #pragma unroll
        for (int i = 0; i < 4; i++) {
            int idx = tid + i * 256;
            int row = idx >> 4;
            int c4  = (idx & 15) * 4;
            float4 kv = *(const float4*)&Kr[row * LDR + c4];
            float4 vv = *(const float4*)&Vr[row * LDR + c4];
            *(uint4*)&Ks[row * LDK + c4] =
                make_uint4(f2tf(kv.x), f2tf(kv.y), f2tf(kv.z), f2tf(kv.w));
            *(uint4*)&Vs[row * LDV + c4] =
                make_uint4(f2tf(vv.x), f2tf(vv.y), f2tf(vv.z), f2tf(vv.w));
        }
    };

    stage_kv(0);
    CPA_COMMIT();

    // Q fragments (pre-scaled by 1/8)
    uint32_t qa[8][4];
    {
        const float* qp = qkv + (size_t)(b * SEQ + qbase) * QKV_N + h * HDIM;
        #pragma unroll
        for (int ks = 0; ks < 8; ks++) {
            int d = ks * 8 + c0;
            qa[ks][0] = f2tf(0.125f * qp[(size_t)r0 * QKV_N + d]);
            qa[ks][1] = f2tf(0.125f * qp[(size_t)(r0 + 8) * QKV_N + d]);
            qa[ks][2] = f2tf(0.125f * qp[(size_t)r0 * QKV_N + d + 4]);
            qa[ks][3] = f2tf(0.125f * qp[(size_t)(r0 + 8) * QKV_N + d + 4]);
        }
    }

    float o[8][4];
    #pragma unroll
    for (int ni = 0; ni < 8; ni++)
        #pragma unroll
        for (int j = 0; j < 4; j++) o[ni][j] = 0.f;
    float m0 = -1e30f, m1 = -1e30f, l0 = 0.f, l1 = 0.f;

    // prologue: finish tile 0 staging + convert
    CPA_WAIT(0);
    __syncthreads();
    convert_kv();
    __syncthreads();

    for (int kt = 0; kt < SEQ / 64; kt++) {
        // prefetch next tile into raw staging (overlaps compute below)
        if (kt + 1 < SEQ / 64) stage_kv(kt + 1);
        CPA_COMMIT();

        // S = Q K^T  (16 x 64 per warp)
        float s[8][4];
        #pragma unroll
        for (int ni = 0; ni < 8; ni++)
            #pragma unroll
            for (int j = 0; j < 4; j++) s[ni][j] = 0.f;

        #pragma unroll
        for (int ks = 0; ks < 8; ks++) {
            int d = ks * 8 + c0;
            #pragma unroll
            for (int ni = 0; ni < 8; ni++) {
                int kvr = ni * 8 + r0;
                uint32_t b0 = Ks[kvr * LDK + d];
                uint32_t b1 = Ks[kvr * LDK + d + 4];
                mma8(s[ni], qa[ks][0], qa[ks][1], qa[ks][2], qa[ks][3], b0, b1);
            }
        }

        // online softmax
        float tm0 = -1e30f, tm1 = -1e30f;
        #pragma unroll
        for (int ni = 0; ni < 8; ni++) {
            tm0 = fmaxf(tm0, fmaxf(s[ni][0], s[ni][1]));
            tm1 = fmaxf(tm1, fmaxf(s[ni][2], s[ni][3]));
        }
        tm0 = fmaxf(tm0, __shfl_xor_sync(0xffffffffu, tm0, 1));
        tm0 = fmaxf(tm0, __shfl_xor_sync(0xffffffffu, tm0, 2));
        tm1 = fmaxf(tm1, __shfl_xor_sync(0xffffffffu, tm1, 1));
        tm1 = fmaxf(tm1, __shfl_xor_sync(0xffffffffu, tm1, 2));

        float nm0 = fmaxf(m0, tm0), nm1 = fmaxf(m1, tm1);
        float cor0 = __expf(m0 - nm0), cor1 = __expf(m1 - nm1);
        m0 = nm0; m1 = nm1;
        l0 *= cor0; l1 *= cor1;
        #pragma unroll
        for (int ni = 0; ni < 8; ni++) {
            o[ni][0] *= cor0; o[ni][1] *= cor0;
            o[ni][2] *= cor1; o[ni][3] *= cor1;
        }

        __syncwarp();
        #pragma unroll
        for (int ni = 0; ni < 8; ni++) {
            float p0 = __expf(s[ni][0] - nm0);
            float p1 = __expf(s[ni][1] - nm0);
            float p2 = __expf(s[ni][2] - nm1);
            float p3 = __expf(s[ni][3] - nm1);
            l0 += p0 + p1;
            l1 += p2 + p3;
            int col = ni * 8 + c0 * 2;
            *(uint2*)&Pw[r0 * LDP + col]       = make_uint2(f2tf(p0), f2tf(p1));
            *(uint2*)&Pw[(r0 + 8) * LDP + col] = make_uint2(f2tf(p2), f2tf(p3));
        }
        __syncwarp();

        // O += P V
        #pragma unroll
        for (int ks = 0; ks < 8; ks++) {
            int kvl = ks * 8;
            uint32_t a0 = Pw[r0 * LDP + kvl + c0];
            uint32_t a1 = Pw[(r0 + 8) * LDP + kvl + c0];
            uint32_t a2 = Pw[r0 * LDP + kvl + c0 + 4];
            uint32_t a3 = Pw[(r0 + 8) * LDP + kvl + c0 + 4];
            #pragma unroll
            for (int ni = 0; ni < 8; ni++) {
                int d = ni * 8 + r0;
                uint32_t b0 = Vs[(kvl + c0) * LDV + d];
                uint32_t b1 = Vs[(kvl + c0 + 4) * LDV + d];
                mma8(o[ni], a0, a1, a2, a3, b0, b1);
            }
        }

        // fold in next tile: wait staging, convert
        if (kt + 1 < SEQ / 64) {
            CPA_WAIT(0);
            __syncthreads();          // all warps done reading Ks/Vs + staging ready
            convert_kv();
            __syncthreads();
        }
    }

    // finalize
    l0 += __shfl_xor_sync(0xffffffffu, l0, 1);
    l0 += __shfl_xor_sync(0xffffffffu, l0, 2);
    l1 += __shfl_xor_sync(0xffffffffu, l1, 1);
    l1 += __shfl_xor_sync(0xffffffffu, l1, 2);
    float inv0 = 1.f / l0, inv1 = 1.f / l1;

    float* op = out + (size_t)(b * SEQ + qbase) * DIM + h * HDIM;
    #pragma unroll
    for (int ni = 0; ni < 8; ni++) {
        int d = ni * 8 + c0 * 2;
        *(float2*)&op[(size_t)r0 * DIM + d] =
            make_float2(o[ni][0] * inv0, o[ni][1] * inv0);
        *(float2*)&op[(size_t)(r0 + 8) * DIM + d] =
            make_float2(o[ni][2] * inv1, o[ni][3] * inv1);
    }
}

// ---------------------------------------------------------------------------
extern "C" void kernel_launch(void* const* d_in, const int* in_sizes, int n_in,
                              void* d_out, int out_size)
{
    const float* x      = (const float*)d_in[0];
    const float* w_qkv  = (const float*)d_in[1];
    const float* w_proj = (const float*)d_in[2];
    const float* b_proj = (const float*)d_in[3];
    float* out = (float*)d_out;

    float* qkv = nullptr;
    float* att = nullptr;
    cudaGetSymbolAddress((void**)&qkv, g_qkv);
    cudaGetSymbolAddress((void**)&att, g_att);

    cudaFuncSetAttribute(gemm_tf32, cudaFuncAttributeMaxDynamicSharedMemorySize, GEMM_SMEM);
    cudaFuncSetAttribute(attn_tf32, cudaFuncAttributeMaxDynamicSharedMemorySize, ATTN_SMEM);

    gemm_tf32<<<dim3(QKV_N / 128, M_TOT / 128), 256, GEMM_SMEM>>>(x, w_qkv, nullptr, qkv, QKV_N, DIM);
    attn_tf32<<<dim3(SEQ / 128, HEADS, BATCH), 256, ATTN_SMEM>>>(qkv, att);
    gemm_tf32<<<dim3(DIM / 128, M_TOT / 128), 256, GEMM_SMEM>>>(att, w_proj, b_proj, out, DIM, DIM);
}

// round 6
// speedup vs baseline: 2.5495x; 1.0016x over previous
#include <cuda_runtime.h>
#include <cstdint>

#define BATCH   4
#define SEQ     2048
#define DIM     768
#define HEADS   12
#define HDIM    64
#define M_TOT   8192
#define QKV_N   2304

// Scratch (device globals: allocation-guard-safe)
__device__ float    g_qkv[(size_t)M_TOT * QKV_N];        // raw qkv
__device__ uint32_t g_xhi[(size_t)M_TOT * DIM];
__device__ uint32_t g_xlo[(size_t)M_TOT * DIM];
__device__ uint32_t g_wqkvhi[(size_t)DIM * QKV_N];
__device__ uint32_t g_wqkvlo[(size_t)DIM * QKV_N];
__device__ uint32_t g_wprojhi[(size_t)DIM * DIM];
__device__ uint32_t g_wprojlo[(size_t)DIM * DIM];
__device__ uint32_t g_atthi[(size_t)M_TOT * DIM];
__device__ uint32_t g_attlo[(size_t)M_TOT * DIM];

// ---------------------------------------------------------------------------
// helpers
// ---------------------------------------------------------------------------
__device__ __forceinline__ uint32_t f2tf(float x) {
    uint32_t u;
    asm("cvt.rna.tf32.f32 %0, %1;" : "=r"(u) : "f"(x));
    return u;
}

__device__ __forceinline__ void mma8(float* c,
                                     uint32_t a0, uint32_t a1, uint32_t a2, uint32_t a3,
                                     uint32_t b0, uint32_t b1) {
    asm volatile(
        "mma.sync.aligned.m16n8k8.row.col.f32.tf32.tf32.f32 "
        "{%0,%1,%2,%3},{%4,%5,%6,%7},{%8,%9},{%0,%1,%2,%3};"
        : "+f"(c[0]), "+f"(c[1]), "+f"(c[2]), "+f"(c[3])
        : "r"(a0), "r"(a1), "r"(a2), "r"(a3), "r"(b0), "r"(b1));
}

__device__ __forceinline__ void cpa16(void* dst, const void* src) {
    uint32_t d = (uint32_t)__cvta_generic_to_shared(dst);
    asm volatile("cp.async.cg.shared.global [%0], [%1], 16;\n" :: "r"(d), "l"(src));
}
#define CPA_COMMIT()  asm volatile("cp.async.commit_group;\n" ::)
#define CPA_WAIT(n)   asm volatile("cp.async.wait_group %0;\n" :: "n"(n))

// ---------------------------------------------------------------------------
// Splitter: src float -> (hi, lo) tf32 pair, vectorized by 4.
// ---------------------------------------------------------------------------
__global__ __launch_bounds__(256)
void split_tf32(const float* __restrict__ src, uint32_t* __restrict__ hi,
                uint32_t* __restrict__ lo, int n4)
{
    int i = blockIdx.x * 256 + threadIdx.x;
    if (i >= n4) return;
    float4 v = ((const float4*)src)[i];
    uint4 h, l;
    h.x = f2tf(v.x); l.x = f2tf(v.x - __uint_as_float(h.x));
    h.y = f2tf(v.y); l.y = f2tf(v.y - __uint_as_float(h.y));
    h.z = f2tf(v.z); l.z = f2tf(v.z - __uint_as_float(h.z));
    h.w = f2tf(v.w); l.w = f2tf(v.w - __uint_as_float(h.w));
    ((uint4*)hi)[i] = h;
    ((uint4*)lo)[i] = l;
}

// ---------------------------------------------------------------------------
// 3xTF32 GEMM on PRE-SPLIT operands. BM=128 BN=128 BK=16, 256 thr, 8 warps.
// 3-stage cp.async pipeline; inner loop is pure LDS + mma (no cvt).
// A smem m-major (ld=20), B smem n-major (ld=136), hi+lo copies of each.
// ---------------------------------------------------------------------------
#define LDA 20
#define LDB 136
#define A_HALF (128 * LDA)
#define B_HALF (16 * LDB)
#define STG_W  (2 * A_HALF + 2 * B_HALF)           // words per stage
#define GEMM_SMEM (3 * STG_W * 4)

__global__ __launch_bounds__(256, 2)
void gemm_tf32(const uint32_t* __restrict__ Ahi, const uint32_t* __restrict__ Alo,
               const uint32_t* __restrict__ Bhi, const uint32_t* __restrict__ Blo,
               const float* __restrict__ bias, float* __restrict__ C,
               int N, int K)
{
    extern __shared__ uint32_t gsm[];

    const int tid  = threadIdx.x;
    const int lane = tid & 31;
    const int wid  = tid >> 5;
    const int wm   = wid >> 1;          // 0..3
    const int wn   = wid & 1;           // 0..1
    const int r0   = lane >> 2;
    const int c0   = lane & 3;
    const int bx   = blockIdx.x;
    const int by   = blockIdx.y;
    const int nt   = K / 16;

    auto prefetch = [&](int t, int s) {
        uint32_t* Ah = gsm + s * STG_W;
        uint32_t* Al = Ah + A_HALF;
        uint32_t* Bh = Al + A_HALF;
        uint32_t* Bl = Bh + B_HALF;
        #pragma unroll
        for (int i = 0; i < 2; i++) {
            int idx = tid + i * 256;                 // 0..511
            int ar = idx >> 2, ac4 = (idx & 3) * 4;
            size_t asrc = (size_t)(by * 128 + ar) * K + t * 16 + ac4;
            cpa16(Ah + ar * LDA + ac4, Ahi + asrc);
            cpa16(Al + ar * LDA + ac4, Alo + asrc);
            int bk = idx >> 5, bc4 = (idx & 31) * 4;
            size_t bsrc = (size_t)(t * 16 + bk) * N + bx * 128 + bc4;
            cpa16(Bh + bk * LDB + bc4, Bhi + bsrc);
            cpa16(Bl + bk * LDB + bc4, Blo + bsrc);
        }
    };

    float acc[2][8][4];
    #pragma unroll
    for (int mi = 0; mi < 2; mi++)
        #pragma unroll
        for (int ni = 0; ni < 8; ni++)
            #pragma unroll
            for (int j = 0; j < 4; j++) acc[mi][ni][j] = 0.f;

    prefetch(0, 0); CPA_COMMIT();
    prefetch(1, 1); CPA_COMMIT();

    for (int it = 0; it < nt; it++) {
        CPA_WAIT(1);
        __syncthreads();
        if (it + 2 < nt) prefetch(it + 2, (it + 2) % 3);
        CPA_COMMIT();

        const uint32_t* Ah = gsm + (it % 3) * STG_W;
        const uint32_t* Al = Ah + A_HALF;
        const uint32_t* Bh = Al + A_HALF;
        const uint32_t* Bl = Bh + B_HALF;

        #pragma unroll
        for (int ks = 0; ks < 2; ks++) {
            const int k = ks * 8 + c0;
            uint32_t ah[2][4], al[2][4];
            #pragma unroll
            for (int mi = 0; mi < 2; mi++) {
                int m = wm * 32 + mi * 16 + r0;
                ah[mi][0] = Ah[m * LDA + k];
                ah[mi][1] = Ah[(m + 8) * LDA + k];
                ah[mi][2] = Ah[m * LDA + k + 4];
                ah[mi][3] = Ah[(m + 8) * LDA + k + 4];
                al[mi][0] = Al[m * LDA + k];
                al[mi][1] = Al[(m + 8) * LDA + k];
                al[mi][2] = Al[m * LDA + k + 4];
                al[mi][3] = Al[(m + 8) * LDA + k + 4];
            }
            #pragma unroll
            for (int ni = 0; ni < 8; ni++) {
                int n = wn * 64 + ni * 8 + r0;
                uint32_t bh0 = Bh[k * LDB + n];
                uint32_t bh1 = Bh[(k + 4) * LDB + n];
                uint32_t bl0 = Bl[k * LDB + n];
                uint32_t bl1 = Bl[(k + 4) * LDB + n];
                #pragma unroll
                for (int mi = 0; mi < 2; mi++) {
                    mma8(acc[mi][ni], ah[mi][0], ah[mi][1], ah[mi][2], ah[mi][3], bh0, bh1);
                    mma8(acc[mi][ni], ah[mi][0], ah[mi][1], ah[mi][2], ah[mi][3], bl0, bl1);
                    mma8(acc[mi][ni], al[mi][0], al[mi][1], al[mi][2], al[mi][3], bh0, bh1);
                }
            }
        }
        __syncthreads();
    }

    // epilogue
    #pragma unroll
    for (int mi = 0; mi < 2; mi++) {
        int r = by * 128 + wm * 32 + mi * 16 + r0;
        #pragma unroll
        for (int ni = 0; ni < 8; ni++) {
            int cc = bx * 128 + wn * 64 + ni * 8 + c0 * 2;
            float bb0 = bias ? bias[cc] : 0.f;
            float bb1 = bias ? bias[cc + 1] : 0.f;
            *(float2*)(C + (size_t)r * N + cc) =
                make_float2(acc[mi][ni][0] + bb0, acc[mi][ni][1] + bb1);
            *(float2*)(C + (size_t)(r + 8) * N + cc) =
                make_float2(acc[mi][ni][2] + bb0, acc[mi][ni][3] + bb1);
        }
    }
}

// ---------------------------------------------------------------------------
// tf32 flash attention with cp.async K/V prefetch overlap (unchanged from R5
// except the epilogue writes pre-split hi/lo outputs for the proj GEMM).
// ---------------------------------------------------------------------------
#define LDR 68
#define LDK 76
#define LDV 72
#define LDP 68
#define ATTN_SMEM ((2 * 64 * LDR + 64 * LDK + 64 * LDV + 128 * LDP) * 4)

__global__ __launch_bounds__(256, 2)
void attn_tf32(const float* __restrict__ qkv,
               uint32_t* __restrict__ atthi, uint32_t* __restrict__ attlo)
{
    extern __shared__ float smf[];
    float* Kr = smf;
    float* Vr = smf + 64 * LDR;
    uint32_t* Ks = (uint32_t*)(smf + 2 * 64 * LDR);
    uint32_t* Vs = Ks + 64 * LDK;
    uint32_t* Ps = Vs + 64 * LDV;

    const int tid  = threadIdx.x;
    const int lane = tid & 31;
    const int wid  = tid >> 5;
    const int b    = blockIdx.z;
    const int h    = blockIdx.y;
    const int qbase = blockIdx.x * 128 + wid * 16;
    const int r0 = lane >> 2;
    const int c0 = lane & 3;
    uint32_t* Pw = Ps + wid * 16 * LDP;

    auto stage_kv = [&](int kt) {
        #pragma unroll
        for (int i = 0; i < 4; i++) {
            int idx = tid + i * 256;
            int row = idx >> 4;
            int c4  = (idx & 15) * 4;
            const float* base = qkv + (size_t)(b * SEQ + kt * 64 + row) * QKV_N
                                + h * HDIM + c4;
            cpa16(Kr + row * LDR + c4, base + DIM);
            cpa16(Vr + row * LDR + c4, base + 2 * DIM);
        }
    };
    auto convert_kv = [&]() {
        #pragma unroll
        for (int i = 0; i < 4; i++) {
            int idx = tid + i * 256;
            int row = idx >> 4;
            int c4  = (idx & 15) * 4;
            float4 kv = *(const float4*)&Kr[row * LDR + c4];
            float4 vv = *(const float4*)&Vr[row * LDR + c4];
            *(uint4*)&Ks[row * LDK + c4] =
                make_uint4(f2tf(kv.x), f2tf(kv.y), f2tf(kv.z), f2tf(kv.w));
            *(uint4*)&Vs[row * LDV + c4] =
                make_uint4(f2tf(vv.x), f2tf(vv.y), f2tf(vv.z), f2tf(vv.w));
        }
    };

    stage_kv(0);
    CPA_COMMIT();

    uint32_t qa[8][4];
    {
        const float* qp = qkv + (size_t)(b * SEQ + qbase) * QKV_N + h * HDIM;
        #pragma unroll
        for (int ks = 0; ks < 8; ks++) {
            int d = ks * 8 + c0;
            qa[ks][0] = f2tf(0.125f * qp[(size_t)r0 * QKV_N + d]);
            qa[ks][1] = f2tf(0.125f * qp[(size_t)(r0 + 8) * QKV_N + d]);
            qa[ks][2] = f2tf(0.125f * qp[(size_t)r0 * QKV_N + d + 4]);
            qa[ks][3] = f2tf(0.125f * qp[(size_t)(r0 + 8) * QKV_N + d + 4]);
        }
    }

    float o[8][4];
    #pragma unroll
    for (int ni = 0; ni < 8; ni++)
        #pragma unroll
        for (int j = 0; j < 4; j++) o[ni][j] = 0.f;
    float m0 = -1e30f, m1 = -1e30f, l0 = 0.f, l1 = 0.f;

    CPA_WAIT(0);
    __syncthreads();
    convert_kv();
    __syncthreads();

    for (int kt = 0; kt < SEQ / 64; kt++) {
        if (kt + 1 < SEQ / 64) stage_kv(kt + 1);
        CPA_COMMIT();

        float s[8][4];
        #pragma unroll
        for (int ni = 0; ni < 8; ni++)
            #pragma unroll
            for (int j = 0; j < 4; j++) s[ni][j] = 0.f;

        #pragma unroll
        for (int ks = 0; ks < 8; ks++) {
            int d = ks * 8 + c0;
            #pragma unroll
            for (int ni = 0; ni < 8; ni++) {
                int kvr = ni * 8 + r0;
                uint32_t b0 = Ks[kvr * LDK + d];
                uint32_t b1 = Ks[kvr * LDK + d + 4];
                mma8(s[ni], qa[ks][0], qa[ks][1], qa[ks][2], qa[ks][3], b0, b1);
            }
        }

        float tm0 = -1e30f, tm1 = -1e30f;
        #pragma unroll
        for (int ni = 0; ni < 8; ni++) {
            tm0 = fmaxf(tm0, fmaxf(s[ni][0], s[ni][1]));
            tm1 = fmaxf(tm1, fmaxf(s[ni][2], s[ni][3]));
        }
        tm0 = fmaxf(tm0, __shfl_xor_sync(0xffffffffu, tm0, 1));
        tm0 = fmaxf(tm0, __shfl_xor_sync(0xffffffffu, tm0, 2));
        tm1 = fmaxf(tm1, __shfl_xor_sync(0xffffffffu, tm1, 1));
        tm1 = fmaxf(tm1, __shfl_xor_sync(0xffffffffu, tm1, 2));

        float nm0 = fmaxf(m0, tm0), nm1 = fmaxf(m1, tm1);
        float cor0 = __expf(m0 - nm0), cor1 = __expf(m1 - nm1);
        m0 = nm0; m1 = nm1;
        l0 *= cor0; l1 *= cor1;
        #pragma unroll
        for (int ni = 0; ni < 8; ni++) {
            o[ni][0] *= cor0; o[ni][1] *= cor0;
            o[ni][2] *= cor1; o[ni][3] *= cor1;
        }

        __syncwarp();
        #pragma unroll
        for (int ni = 0; ni < 8; ni++) {
            float p0 = __expf(s[ni][0] - nm0);
            float p1 = __expf(s[ni][1] - nm0);
            float p2 = __expf(s[ni][2] - nm1);
            float p3 = __expf(s[ni][3] - nm1);
            l0 += p0 + p1;
            l1 += p2 + p3;
            int col = ni * 8 + c0 * 2;
            *(uint2*)&Pw[r0 * LDP + col]       = make_uint2(f2tf(p0), f2tf(p1));
            *(uint2*)&Pw[(r0 + 8) * LDP + col] = make_uint2(f2tf(p2), f2tf(p3));
        }
        __syncwarp();

        #pragma unroll
        for (int ks = 0; ks < 8; ks++) {
            int kvl = ks * 8;
            uint32_t a0 = Pw[r0 * LDP + kvl + c0];
            uint32_t a1 = Pw[(r0 + 8) * LDP + kvl + c0];
            uint32_t a2 = Pw[r0 * LDP + kvl + c0 + 4];
            uint32_t a3 = Pw[(r0 + 8) * LDP + kvl + c0 + 4];
            #pragma unroll
            for (int ni = 0; ni < 8; ni++) {
                int d = ni * 8 + r0;
                uint32_t b0 = Vs[(kvl + c0) * LDV + d];
                uint32_t b1 = Vs[(kvl + c0 + 4) * LDV + d];
                mma8(o[ni], a0, a1, a2, a3, b0, b1);
            }
        }

        if (kt + 1 < SEQ / 64) {
            CPA_WAIT(0);
            __syncthreads();
            convert_kv();
            __syncthreads();
        }
    }

    l0 += __shfl_xor_sync(0xffffffffu, l0, 1);
    l0 += __shfl_xor_sync(0xffffffffu, l0, 2);
    l1 += __shfl_xor_sync(0xffffffffu, l1, 1);
    l1 += __shfl_xor_sync(0xffffffffu, l1, 2);
    float inv0 = 1.f / l0, inv1 = 1.f / l1;

    // epilogue: write pre-split tf32 hi/lo for the proj GEMM
    size_t rbase = (size_t)(b * SEQ + qbase) * DIM + h * HDIM;
    #pragma unroll
    for (int ni = 0; ni < 8; ni++) {
        int d = ni * 8 + c0 * 2;
        float v0 = o[ni][0] * inv0, v1 = o[ni][1] * inv0;
        float v2 = o[ni][2] * inv1, v3 = o[ni][3] * inv1;
        uint32_t h0 = f2tf(v0), h1 = f2tf(v1), h2 = f2tf(v2), h3 = f2tf(v3);
        size_t i0 = rbase + (size_t)r0 * DIM + d;
        size_t i1 = rbase + (size_t)(r0 + 8) * DIM + d;
        *(uint2*)&atthi[i0] = make_uint2(h0, h1);
        *(uint2*)&attlo[i0] = make_uint2(f2tf(v0 - __uint_as_float(h0)),
                                         f2tf(v1 - __uint_as_float(h1)));
        *(uint2*)&atthi[i1] = make_uint2(h2, h3);
        *(uint2*)&attlo[i1] = make_uint2(f2tf(v2 - __uint_as_float(h2)),
                                         f2tf(v3 - __uint_as_float(h3)));
    }
}

// ---------------------------------------------------------------------------
extern "C" void kernel_launch(void* const* d_in, const int* in_sizes, int n_in,
                              void* d_out, int out_size)
{
    const float* x      = (const float*)d_in[0];
    const float* w_qkv  = (const float*)d_in[1];
    const float* w_proj = (const float*)d_in[2];
    const float* b_proj = (const float*)d_in[3];
    float* out = (float*)d_out;

    float *qkv;
    uint32_t *xhi, *xlo, *wqh, *wql, *wph, *wpl, *athi, *atlo;
    cudaGetSymbolAddress((void**)&qkv,  g_qkv);
    cudaGetSymbolAddress((void**)&xhi,  g_xhi);
    cudaGetSymbolAddress((void**)&xlo,  g_xlo);
    cudaGetSymbolAddress((void**)&wqh,  g_wqkvhi);
    cudaGetSymbolAddress((void**)&wql,  g_wqkvlo);
    cudaGetSymbolAddress((void**)&wph,  g_wprojhi);
    cudaGetSymbolAddress((void**)&wpl,  g_wprojlo);
    cudaGetSymbolAddress((void**)&athi, g_atthi);
    cudaGetSymbolAddress((void**)&atlo, g_attlo);

    cudaFuncSetAttribute(gemm_tf32, cudaFuncAttributeMaxDynamicSharedMemorySize, GEMM_SMEM);
    cudaFuncSetAttribute(attn_tf32, cudaFuncAttributeMaxDynamicSharedMemorySize, ATTN_SMEM);

    // 0) pre-split inputs into tf32 hi/lo
    split_tf32<<<(M_TOT * DIM / 4 + 255) / 256, 256>>>(x, xhi, xlo, M_TOT * DIM / 4);
    split_tf32<<<(DIM * QKV_N / 4 + 255) / 256, 256>>>(w_qkv, wqh, wql, DIM * QKV_N / 4);
    split_tf32<<<(DIM * DIM / 4 + 255) / 256, 256>>>(w_proj, wph, wpl, DIM * DIM / 4);

    // 1) qkv = x @ w_qkv
    gemm_tf32<<<dim3(QKV_N / 128, M_TOT / 128), 256, GEMM_SMEM>>>(
        xhi, xlo, wqh, wql, nullptr, qkv, QKV_N, DIM);
    // 2) attention -> att (hi/lo)
    attn_tf32<<<dim3(SEQ / 128, HEADS, BATCH), 256, ATTN_SMEM>>>(qkv, athi, atlo);
    // 3) out = att @ w_proj + b
    gemm_tf32<<<dim3(DIM / 128, M_TOT / 128), 256, GEMM_SMEM>>>(
        athi, atlo, wph, wpl, b_proj, out, DIM, DIM);
}

// round 7
// speedup vs baseline: 2.5713x; 1.0086x over previous
#include <cuda_runtime.h>
#include <cstdint>

#define BATCH   4
#define SEQ     2048
#define DIM     768
#define HEADS   12
#define HDIM    64
#define M_TOT   8192
#define QKV_N   2304

// Scratch (device globals: allocation-guard-safe)
__device__ float    g_qkv[(size_t)M_TOT * QKV_N];
__device__ uint32_t g_xhi[(size_t)M_TOT * DIM];
__device__ uint32_t g_xlo[(size_t)M_TOT * DIM];
__device__ uint32_t g_wqkvhi[(size_t)DIM * QKV_N];
__device__ uint32_t g_wqkvlo[(size_t)DIM * QKV_N];
__device__ uint32_t g_wprojhi[(size_t)DIM * DIM];
__device__ uint32_t g_wprojlo[(size_t)DIM * DIM];
__device__ uint32_t g_atthi[(size_t)M_TOT * DIM];
__device__ uint32_t g_attlo[(size_t)M_TOT * DIM];

// ---------------------------------------------------------------------------
// helpers
// ---------------------------------------------------------------------------
__device__ __forceinline__ uint32_t f2tf(float x) {
    uint32_t u;
    asm("cvt.rna.tf32.f32 %0, %1;" : "=r"(u) : "f"(x));
    return u;
}

__device__ __forceinline__ void mma8(float* c,
                                     uint32_t a0, uint32_t a1, uint32_t a2, uint32_t a3,
                                     uint32_t b0, uint32_t b1) {
    asm volatile(
        "mma.sync.aligned.m16n8k8.row.col.f32.tf32.tf32.f32 "
        "{%0,%1,%2,%3},{%4,%5,%6,%7},{%8,%9},{%0,%1,%2,%3};"
        : "+f"(c[0]), "+f"(c[1]), "+f"(c[2]), "+f"(c[3])
        : "r"(a0), "r"(a1), "r"(a2), "r"(a3), "r"(b0), "r"(b1));
}

__device__ __forceinline__ void cpa16(void* dst, const void* src) {
    uint32_t d = (uint32_t)__cvta_generic_to_shared(dst);
    asm volatile("cp.async.cg.shared.global [%0], [%1], 16;\n" :: "r"(d), "l"(src));
}
#define CPA_COMMIT()  asm volatile("cp.async.commit_group;\n" ::)
#define CPA_WAIT(n)   asm volatile("cp.async.wait_group %0;\n" :: "n"(n))

// ---------------------------------------------------------------------------
// Splitter: src float -> (hi, lo) tf32 pair, vectorized by 4.
// ---------------------------------------------------------------------------
__global__ __launch_bounds__(256)
void split_tf32(const float* __restrict__ src, uint32_t* __restrict__ hi,
                uint32_t* __restrict__ lo, int n4)
{
    int i = blockIdx.x * 256 + threadIdx.x;
    if (i >= n4) return;
    float4 v = ((const float4*)src)[i];
    uint4 h, l;
    h.x = f2tf(v.x); l.x = f2tf(v.x - __uint_as_float(h.x));
    h.y = f2tf(v.y); l.y = f2tf(v.y - __uint_as_float(h.y));
    h.z = f2tf(v.z); l.z = f2tf(v.z - __uint_as_float(h.z));
    h.w = f2tf(v.w); l.w = f2tf(v.w - __uint_as_float(h.w));
    ((uint4*)hi)[i] = h;
    ((uint4*)lo)[i] = l;
}

// ---------------------------------------------------------------------------
// 3xTF32 GEMM on PRE-SPLIT operands. BM=128 BN=128 BK=16, 256 thr, 8 warps.
// 3-stage cp.async pipeline, ONE barrier per k-step.
// ---------------------------------------------------------------------------
#define LDA 20
#define LDB 136
#define A_HALF (128 * LDA)
#define B_HALF (16 * LDB)
#define STG_W  (2 * A_HALF + 2 * B_HALF)
#define GEMM_SMEM (3 * STG_W * 4)

__global__ __launch_bounds__(256, 2)
void gemm_tf32(const uint32_t* __restrict__ Ahi, const uint32_t* __restrict__ Alo,
               const uint32_t* __restrict__ Bhi, const uint32_t* __restrict__ Blo,
               const float* __restrict__ bias, float* __restrict__ C,
               int N, int K)
{
    extern __shared__ uint32_t gsm[];

    const int tid  = threadIdx.x;
    const int lane = tid & 31;
    const int wid  = tid >> 5;
    const int wm   = wid >> 1;
    const int wn   = wid & 1;
    const int r0   = lane >> 2;
    const int c0   = lane & 3;
    const int bx   = blockIdx.x;
    const int by   = blockIdx.y;
    const int nt   = K / 16;

    auto prefetch = [&](int t, int s) {
        uint32_t* Ah = gsm + s * STG_W;
        uint32_t* Al = Ah + A_HALF;
        uint32_t* Bh = Al + A_HALF;
        uint32_t* Bl = Bh + B_HALF;
        #pragma unroll
        for (int i = 0; i < 2; i++) {
            int idx = tid + i * 256;
            int ar = idx >> 2, ac4 = (idx & 3) * 4;
            size_t asrc = (size_t)(by * 128 + ar) * K + t * 16 + ac4;
            cpa16(Ah + ar * LDA + ac4, Ahi + asrc);
            cpa16(Al + ar * LDA + ac4, Alo + asrc);
            int bk = idx >> 5, bc4 = (idx & 31) * 4;
            size_t bsrc = (size_t)(t * 16 + bk) * N + bx * 128 + bc4;
            cpa16(Bh + bk * LDB + bc4, Bhi + bsrc);
            cpa16(Bl + bk * LDB + bc4, Blo + bsrc);
        }
    };

    float acc[2][8][4];
    #pragma unroll
    for (int mi = 0; mi < 2; mi++)
        #pragma unroll
        for (int ni = 0; ni < 8; ni++)
            #pragma unroll
            for (int j = 0; j < 4; j++) acc[mi][ni][j] = 0.f;

    prefetch(0, 0); CPA_COMMIT();
    prefetch(1, 1); CPA_COMMIT();

    for (int it = 0; it < nt; it++) {
        CPA_WAIT(1);
        __syncthreads();      // stage it%3 ready AND all warps done with it-1's data
        if (it + 2 < nt) prefetch(it + 2, (it + 2) % 3);
        CPA_COMMIT();

        const uint32_t* Ah = gsm + (it % 3) * STG_W;
        const uint32_t* Al = Ah + A_HALF;
        const uint32_t* Bh = Al + A_HALF;
        const uint32_t* Bl = Bh + B_HALF;

        #pragma unroll
        for (int ks = 0; ks < 2; ks++) {
            const int k = ks * 8 + c0;
            uint32_t ah[2][4], al[2][4];
            #pragma unroll
            for (int mi = 0; mi < 2; mi++) {
                int m = wm * 32 + mi * 16 + r0;
                ah[mi][0] = Ah[m * LDA + k];
                ah[mi][1] = Ah[(m + 8) * LDA + k];
                ah[mi][2] = Ah[m * LDA + k + 4];
                ah[mi][3] = Ah[(m + 8) * LDA + k + 4];
                al[mi][0] = Al[m * LDA + k];
                al[mi][1] = Al[(m + 8) * LDA + k];
                al[mi][2] = Al[m * LDA + k + 4];
                al[mi][3] = Al[(m + 8) * LDA + k + 4];
            }
            #pragma unroll
            for (int ni = 0; ni < 8; ni++) {
                int n = wn * 64 + ni * 8 + r0;
                uint32_t bh0 = Bh[k * LDB + n];
                uint32_t bh1 = Bh[(k + 4) * LDB + n];
                uint32_t bl0 = Bl[k * LDB + n];
                uint32_t bl1 = Bl[(k + 4) * LDB + n];
                #pragma unroll
                for (int mi = 0; mi < 2; mi++) {
                    mma8(acc[mi][ni], ah[mi][0], ah[mi][1], ah[mi][2], ah[mi][3], bh0, bh1);
                    mma8(acc[mi][ni], ah[mi][0], ah[mi][1], ah[mi][2], ah[mi][3], bl0, bl1);
                    mma8(acc[mi][ni], al[mi][0], al[mi][1], al[mi][2], al[mi][3], bh0, bh1);
                }
            }
        }
        // no tail barrier: next iteration's head barrier provides the ordering
    }

    #pragma unroll
    for (int mi = 0; mi < 2; mi++) {
        int r = by * 128 + wm * 32 + mi * 16 + r0;
        #pragma unroll
        for (int ni = 0; ni < 8; ni++) {
            int cc = bx * 128 + wn * 64 + ni * 8 + c0 * 2;
            float bb0 = bias ? bias[cc] : 0.f;
            float bb1 = bias ? bias[cc + 1] : 0.f;
            *(float2*)(C + (size_t)r * N + cc) =
                make_float2(acc[mi][ni][0] + bb0, acc[mi][ni][1] + bb1);
            *(float2*)(C + (size_t)(r + 8) * N + cc) =
                make_float2(acc[mi][ni][2] + bb0, acc[mi][ni][3] + bb1);
        }
    }
}

// ---------------------------------------------------------------------------
// tf32 flash attention, double-buffered RAW K/V smem + inline tf32 cvt.
// ONE __syncthreads per KV tile; warps de-phase through S/softmax/PV.
// smem: 2 x (K[64][76] + V[64][72]) raw floats + P[128][68] tf32.
// ---------------------------------------------------------------------------
#define LDK 76
#define LDV 72
#define LDP 68
#define KV_STG (64 * LDK + 64 * LDV)
#define ATTN_SMEM ((2 * KV_STG + 128 * LDP) * 4)
#define NT (SEQ / 64)

__global__ __launch_bounds__(256, 2)
void attn_tf32(const float* __restrict__ qkv,
               uint32_t* __restrict__ atthi, uint32_t* __restrict__ attlo)
{
    extern __shared__ float smf[];
    uint32_t* Ps = (uint32_t*)(smf + 2 * KV_STG);

    const int tid  = threadIdx.x;
    const int lane = tid & 31;
    const int wid  = tid >> 5;
    const int b    = blockIdx.z;
    const int h    = blockIdx.y;
    const int qbase = blockIdx.x * 128 + wid * 16;
    const int r0 = lane >> 2;
    const int c0 = lane & 3;
    uint32_t* Pw = Ps + wid * 16 * LDP;

    auto stage_kv = [&](int kt, int buf) {
        float* Kd = smf + buf * KV_STG;
        float* Vd = Kd + 64 * LDK;
        #pragma unroll
        for (int i = 0; i < 4; i++) {
            int idx = tid + i * 256;
            int row = idx >> 4;
            int c4  = (idx & 15) * 4;
            const float* base = qkv + (size_t)(b * SEQ + kt * 64 + row) * QKV_N
                                + h * HDIM + c4;
            cpa16(Kd + row * LDK + c4, base + DIM);
            cpa16(Vd + row * LDV + c4, base + 2 * DIM);
        }
    };

    stage_kv(0, 0);
    CPA_COMMIT();

    // Q fragments (pre-scaled by 1/8), converted once
    uint32_t qa[8][4];
    {
        const float* qp = qkv + (size_t)(b * SEQ + qbase) * QKV_N + h * HDIM;
        #pragma unroll
        for (int ks = 0; ks < 8; ks++) {
            int d = ks * 8 + c0;
            qa[ks][0] = f2tf(0.125f * qp[(size_t)r0 * QKV_N + d]);
            qa[ks][1] = f2tf(0.125f * qp[(size_t)(r0 + 8) * QKV_N + d]);
            qa[ks][2] = f2tf(0.125f * qp[(size_t)r0 * QKV_N + d + 4]);
            qa[ks][3] = f2tf(0.125f * qp[(size_t)(r0 + 8) * QKV_N + d + 4]);
        }
    }

    float o[8][4];
    #pragma unroll
    for (int ni = 0; ni < 8; ni++)
        #pragma unroll
        for (int j = 0; j < 4; j++) o[ni][j] = 0.f;
    float m0 = -1e30f, m1 = -1e30f, l0 = 0.f, l1 = 0.f;

    CPA_WAIT(0);
    __syncthreads();          // tile 0 visible to all warps

    for (int kt = 0; kt < NT; kt++) {
        const int cur = kt & 1;
        if (kt + 1 < NT) stage_kv(kt + 1, cur ^ 1);
        CPA_COMMIT();

        const float* Kc = smf + cur * KV_STG;
        const float* Vc = Kc + 64 * LDK;

        // S = Q K^T  (inline cvt of raw K)
        float s[8][4];
        #pragma unroll
        for (int ni = 0; ni < 8; ni++)
            #pragma unroll
            for (int j = 0; j < 4; j++) s[ni][j] = 0.f;

        #pragma unroll
        for (int ks = 0; ks < 8; ks++) {
            int d = ks * 8 + c0;
            #pragma unroll
            for (int ni = 0; ni < 8; ni++) {
                int kvr = ni * 8 + r0;
                uint32_t b0 = f2tf(Kc[kvr * LDK + d]);
                uint32_t b1 = f2tf(Kc[kvr * LDK + d + 4]);
                mma8(s[ni], qa[ks][0], qa[ks][1], qa[ks][2], qa[ks][3], b0, b1);
            }
        }

        // online softmax
        float tm0 = -1e30f, tm1 = -1e30f;
        #pragma unroll
        for (int ni = 0; ni < 8; ni++) {
            tm0 = fmaxf(tm0, fmaxf(s[ni][0], s[ni][1]));
            tm1 = fmaxf(tm1, fmaxf(s[ni][2], s[ni][3]));
        }
        tm0 = fmaxf(tm0, __shfl_xor_sync(0xffffffffu, tm0, 1));
        tm0 = fmaxf(tm0, __shfl_xor_sync(0xffffffffu, tm0, 2));
        tm1 = fmaxf(tm1, __shfl_xor_sync(0xffffffffu, tm1, 1));
        tm1 = fmaxf(tm1, __shfl_xor_sync(0xffffffffu, tm1, 2));

        float nm0 = fmaxf(m0, tm0), nm1 = fmaxf(m1, tm1);
        float cor0 = __expf(m0 - nm0), cor1 = __expf(m1 - nm1);
        m0 = nm0; m1 = nm1;
        l0 *= cor0; l1 *= cor1;
        #pragma unroll
        for (int ni = 0; ni < 8; ni++) {
            o[ni][0] *= cor0; o[ni][1] *= cor0;
            o[ni][2] *= cor1; o[ni][3] *= cor1;
        }

        __syncwarp();
        #pragma unroll
        for (int ni = 0; ni < 8; ni++) {
            float p0 = __expf(s[ni][0] - nm0);
            float p1 = __expf(s[ni][1] - nm0);
            float p2 = __expf(s[ni][2] - nm1);
            float p3 = __expf(s[ni][3] - nm1);
            l0 += p0 + p1;
            l1 += p2 + p3;
            int col = ni * 8 + c0 * 2;
            *(uint2*)&Pw[r0 * LDP + col]       = make_uint2(f2tf(p0), f2tf(p1));
            *(uint2*)&Pw[(r0 + 8) * LDP + col] = make_uint2(f2tf(p2), f2tf(p3));
        }
        __syncwarp();

        // O += P V  (inline cvt of raw V)
        #pragma unroll
        for (int ks = 0; ks < 8; ks++) {
            int kvl = ks * 8;
            uint32_t a0 = Pw[r0 * LDP + kvl + c0];
            uint32_t a1 = Pw[(r0 + 8) * LDP + kvl + c0];
            uint32_t a2 = Pw[r0 * LDP + kvl + c0 + 4];
            uint32_t a3 = Pw[(r0 + 8) * LDP + kvl + c0 + 4];
            #pragma unroll
            for (int ni = 0; ni < 8; ni++) {
                int d = ni * 8 + r0;
                uint32_t b0 = f2tf(Vc[(kvl + c0) * LDV + d]);
                uint32_t b1 = f2tf(Vc[(kvl + c0 + 4) * LDV + d]);
                mma8(o[ni], a0, a1, a2, a3, b0, b1);
            }
        }

        if (kt + 1 < NT) {
            CPA_WAIT(0);
            __syncthreads();  // next tile visible; all warps done with cur
        }
    }

    l0 += __shfl_xor_sync(0xffffffffu, l0, 1);
    l0 += __shfl_xor_sync(0xffffffffu, l0, 2);
    l1 += __shfl_xor_sync(0xffffffffu, l1, 1);
    l1 += __shfl_xor_sync(0xffffffffu, l1, 2);
    float inv0 = 1.f / l0, inv1 = 1.f / l1;

    // epilogue: write pre-split tf32 hi/lo for the proj GEMM
    size_t rbase = (size_t)(b * SEQ + qbase) * DIM + h * HDIM;
    #pragma unroll
    for (int ni = 0; ni < 8; ni++) {
        int d = ni * 8 + c0 * 2;
        float v0 = o[ni][0] * inv0, v1 = o[ni][1] * inv0;
        float v2 = o[ni][2] * inv1, v3 = o[ni][3] * inv1;
        uint32_t h0 = f2tf(v0), h1 = f2tf(v1), h2 = f2tf(v2), h3 = f2tf(v3);
        size_t i0 = rbase + (size_t)r0 * DIM + d;
        size_t i1 = rbase + (size_t)(r0 + 8) * DIM + d;
        *(uint2*)&atthi[i0] = make_uint2(h0, h1);
        *(uint2*)&attlo[i0] = make_uint2(f2tf(v0 - __uint_as_float(h0)),
                                         f2tf(v1 - __uint_as_float(h1)));
        *(uint2*)&atthi[i1] = make_uint2(h2, h3);
        *(uint2*)&attlo[i1] = make_uint2(f2tf(v2 - __uint_as_float(h2)),
                                         f2tf(v3 - __uint_as_float(h3)));
    }
}

// ---------------------------------------------------------------------------
extern "C" void kernel_launch(void* const* d_in, const int* in_sizes, int n_in,
                              void* d_out, int out_size)
{
    const float* x      = (const float*)d_in[0];
    const float* w_qkv  = (const float*)d_in[1];
    const float* w_proj = (const float*)d_in[2];
    const float* b_proj = (const float*)d_in[3];
    float* out = (float*)d_out;

    float *qkv;
    uint32_t *xhi, *xlo, *wqh, *wql, *wph, *wpl, *athi, *atlo;
    cudaGetSymbolAddress((void**)&qkv,  g_qkv);
    cudaGetSymbolAddress((void**)&xhi,  g_xhi);
    cudaGetSymbolAddress((void**)&xlo,  g_xlo);
    cudaGetSymbolAddress((void**)&wqh,  g_wqkvhi);
    cudaGetSymbolAddress((void**)&wql,  g_wqkvlo);
    cudaGetSymbolAddress((void**)&wph,  g_wprojhi);
    cudaGetSymbolAddress((void**)&wpl,  g_wprojlo);
    cudaGetSymbolAddress((void**)&athi, g_atthi);
    cudaGetSymbolAddress((void**)&atlo, g_attlo);

    cudaFuncSetAttribute(gemm_tf32, cudaFuncAttributeMaxDynamicSharedMemorySize, GEMM_SMEM);
    cudaFuncSetAttribute(attn_tf32, cudaFuncAttributeMaxDynamicSharedMemorySize, ATTN_SMEM);

    split_tf32<<<(M_TOT * DIM / 4 + 255) / 256, 256>>>(x, xhi, xlo, M_TOT * DIM / 4);
    split_tf32<<<(DIM * QKV_N / 4 + 255) / 256, 256>>>(w_qkv, wqh, wql, DIM * QKV_N / 4);
    split_tf32<<<(DIM * DIM / 4 + 255) / 256, 256>>>(w_proj, wph, wpl, DIM * DIM / 4);

    gemm_tf32<<<dim3(QKV_N / 128, M_TOT / 128), 256, GEMM_SMEM>>>(
        xhi, xlo, wqh, wql, nullptr, qkv, QKV_N, DIM);
    attn_tf32<<<dim3(SEQ / 128, HEADS, BATCH), 256, ATTN_SMEM>>>(qkv, athi, atlo);
    gemm_tf32<<<dim3(DIM / 128, M_TOT / 128), 256, GEMM_SMEM>>>(
        athi, atlo, wph, wpl, b_proj, out, DIM, DIM);
}

// round 9
// speedup vs baseline: 3.2448x; 1.2619x over previous
#include <cuda_runtime.h>
#include <cuda_bf16.h>
#include <cstdint>

#define BATCH   4
#define SEQ     2048
#define DIM     768
#define HEADS   12
#define HDIM    64
#define M_TOT   8192
#define QKV_N   2304

// Scratch (device globals: allocation-guard-safe)
__device__ float    g_qkv[(size_t)M_TOT * QKV_N];
__device__ uint16_t g_xhi[(size_t)M_TOT * DIM];      // bf16 bits, [M][K]
__device__ uint16_t g_xlo[(size_t)M_TOT * DIM];
__device__ uint16_t g_wqkvhi[(size_t)QKV_N * DIM];   // bf16 bits, TRANSPOSED [N][K]
__device__ uint16_t g_wqkvlo[(size_t)QKV_N * DIM];
__device__ uint16_t g_wprojhi[(size_t)DIM * DIM];    // bf16 bits, TRANSPOSED [N][K]
__device__ uint16_t g_wprojlo[(size_t)DIM * DIM];
__device__ uint16_t g_atthi[(size_t)M_TOT * DIM];    // bf16 bits, [M][K]
__device__ uint16_t g_attlo[(size_t)M_TOT * DIM];

// ---------------------------------------------------------------------------
// helpers
// ---------------------------------------------------------------------------
__device__ __forceinline__ uint32_t f2tf(float x) {
    uint32_t u;
    asm("cvt.rna.tf32.f32 %0, %1;" : "=r"(u) : "f"(x));
    return u;
}
__device__ __forceinline__ uint16_t f2bf(float x) {
    return __bfloat16_as_ushort(__float2bfloat16_rn(x));
}
__device__ __forceinline__ float bf2f(uint16_t u) {
    return __bfloat162float(__ushort_as_bfloat16(u));
}

// tf32 m16n8k8 (attention)
__device__ __forceinline__ void mma8(float* c,
                                     uint32_t a0, uint32_t a1, uint32_t a2, uint32_t a3,
                                     uint32_t b0, uint32_t b1) {
    asm volatile(
        "mma.sync.aligned.m16n8k8.row.col.f32.tf32.tf32.f32 "
        "{%0,%1,%2,%3},{%4,%5,%6,%7},{%8,%9},{%0,%1,%2,%3};"
        : "+f"(c[0]), "+f"(c[1]), "+f"(c[2]), "+f"(c[3])
        : "r"(a0), "r"(a1), "r"(a2), "r"(a3), "r"(b0), "r"(b1));
}

// bf16 m16n8k16 (GEMMs)
__device__ __forceinline__ void mma16bf(float* c,
                                        uint32_t a0, uint32_t a1, uint32_t a2, uint32_t a3,
                                        uint32_t b0, uint32_t b1) {
    asm volatile(
        "mma.sync.aligned.m16n8k16.row.col.f32.bf16.bf16.f32 "
        "{%0,%1,%2,%3},{%4,%5,%6,%7},{%8,%9},{%0,%1,%2,%3};"
        : "+f"(c[0]), "+f"(c[1]), "+f"(c[2]), "+f"(c[3])
        : "r"(a0), "r"(a1), "r"(a2), "r"(a3), "r"(b0), "r"(b1));
}

__device__ __forceinline__ void cpa16(void* dst, const void* src) {
    uint32_t d = (uint32_t)__cvta_generic_to_shared(dst);
    asm volatile("cp.async.cg.shared.global [%0], [%1], 16;\n" :: "r"(d), "l"(src));
}
#define CPA_COMMIT()  asm volatile("cp.async.commit_group;\n" ::)
#define CPA_WAIT(n)   asm volatile("cp.async.wait_group %0;\n" :: "n"(n))

// ---------------------------------------------------------------------------
// Splitters: fp32 -> bf16 hi/lo
// ---------------------------------------------------------------------------
__global__ __launch_bounds__(256)
void split_bf16(const float* __restrict__ src, uint16_t* __restrict__ hi,
                uint16_t* __restrict__ lo, int n4)
{
    int i = blockIdx.x * 256 + threadIdx.x;
    if (i >= n4) return;
    float4 v = ((const float4*)src)[i];
    uint16_t h0 = f2bf(v.x), h1 = f2bf(v.y), h2 = f2bf(v.z), h3 = f2bf(v.w);
    uint16_t l0 = f2bf(v.x - bf2f(h0)), l1 = f2bf(v.y - bf2f(h1));
    uint16_t l2 = f2bf(v.z - bf2f(h2)), l3 = f2bf(v.w - bf2f(h3));
    ((uint2*)hi)[i] = make_uint2((uint32_t)h0 | ((uint32_t)h1 << 16),
                                 (uint32_t)h2 | ((uint32_t)h3 << 16));
    ((uint2*)lo)[i] = make_uint2((uint32_t)l0 | ((uint32_t)l1 << 16),
                                 (uint32_t)l2 | ((uint32_t)l3 << 16));
}

// transpose + split: in[K][N] -> hi/lo bf16 [N][K]
__global__ __launch_bounds__(256)
void tsplit_bf16(const float* __restrict__ in, uint16_t* __restrict__ hi,
                 uint16_t* __restrict__ lo, int K, int N)
{
    __shared__ float t[32][33];
    int n0 = blockIdx.x * 32, k0 = blockIdx.y * 32;
    #pragma unroll
    for (int i = threadIdx.y; i < 32; i += 8)
        t[i][threadIdx.x] = in[(size_t)(k0 + i) * N + n0 + threadIdx.x];
    __syncthreads();
    #pragma unroll
    for (int i = threadIdx.y; i < 32; i += 8) {
        float v = t[threadIdx.x][i];
        uint16_t h = f2bf(v);
        size_t o = (size_t)(n0 + i) * K + k0 + threadIdx.x;
        hi[o] = h;
        lo[o] = f2bf(v - bf2f(h));
    }
}

// ---------------------------------------------------------------------------
// 3xBF16 GEMM. BM=128 BN=128 BK=16, 256 thr, 8 warps (4x2), warp tile 32x64.
// A [M][K] bf16 hi/lo; B [N][K] bf16 hi/lo (pre-transposed). 3-stage cp.async.
// smem rows: 8 data words (k-pairs) + 4 pad -> LDW=12, conflict-free frags.
// ---------------------------------------------------------------------------
#define LDW  12
#define MATW (128 * LDW)
#define STGW (4 * MATW)
#define GEMM_SMEM (3 * STGW * 4)

__global__ __launch_bounds__(256, 2)
void gemm_bf16(const uint16_t* __restrict__ Ahi, const uint16_t* __restrict__ Alo,
               const uint16_t* __restrict__ Bhi, const uint16_t* __restrict__ Blo,
               const float* __restrict__ bias, float* __restrict__ C,
               int N, int K)
{
    extern __shared__ uint32_t gsm[];

    const int tid  = threadIdx.x;
    const int lane = tid & 31;
    const int wid  = tid >> 5;
    const int wm   = wid >> 1;
    const int wn   = wid & 1;
    const int r0   = lane >> 2;
    const int c0   = lane & 3;
    const int bx   = blockIdx.x;
    const int by   = blockIdx.y;
    const int nt   = K / 16;
    const int Kw   = K >> 1;          // K in bf16-pair words

    const uint16_t* srcs[4] = {Ahi, Alo, Bhi, Blo};

    auto prefetch = [&](int t, int s) {
        uint32_t* st = gsm + s * STGW;
        #pragma unroll
        for (int i = 0; i < 4; i++) {
            int idx = tid + i * 256;            // 0..1023
            int mat = idx >> 8;                 // 0..3
            int r2  = idx & 255;
            int row = r2 >> 1;                  // 0..127
            int ch  = r2 & 1;                   // 16B chunk
            int rowbase = (mat < 2) ? by * 128 : bx * 128;
            const uint32_t* src = (const uint32_t*)srcs[mat]
                                  + (size_t)(rowbase + row) * Kw + t * 8 + ch * 4;
            cpa16(st + mat * MATW + row * LDW + ch * 4, src);
        }
    };

    float acc[2][8][4];
    #pragma unroll
    for (int mi = 0; mi < 2; mi++)
        #pragma unroll
        for (int ni = 0; ni < 8; ni++)
            #pragma unroll
            for (int j = 0; j < 4; j++) acc[mi][ni][j] = 0.f;

    prefetch(0, 0); CPA_COMMIT();
    prefetch(1, 1); CPA_COMMIT();

    for (int it = 0; it < nt; it++) {
        CPA_WAIT(1);
        __syncthreads();
        if (it + 2 < nt) prefetch(it + 2, (it + 2) % 3);
        CPA_COMMIT();

        const uint32_t* Ah = gsm + (it % 3) * STGW;
        const uint32_t* Al = Ah + MATW;
        const uint32_t* Bh = Al + MATW;
        const uint32_t* Bl = Bh + MATW;

        uint32_t ah[2][4], al[2][4];
        #pragma unroll
        for (int mi = 0; mi < 2; mi++) {
            int m = wm * 32 + mi * 16 + r0;
            ah[mi][0] = Ah[m * LDW + c0];
            ah[mi][1] = Ah[(m + 8) * LDW + c0];
            ah[mi][2] = Ah[m * LDW + c0 + 4];
            ah[mi][3] = Ah[(m + 8) * LDW + c0 + 4];
            al[mi][0] = Al[m * LDW + c0];
            al[mi][1] = Al[(m + 8) * LDW + c0];
            al[mi][2] = Al[m * LDW + c0 + 4];
            al[mi][3] = Al[(m + 8) * LDW + c0 + 4];
        }
        #pragma unroll
        for (int ni = 0; ni < 8; ni++) {
            int n = wn * 64 + ni * 8 + r0;
            uint32_t bh0 = Bh[n * LDW + c0];
            uint32_t bh1 = Bh[n * LDW + c0 + 4];
            uint32_t bl0 = Bl[n * LDW + c0];
            uint32_t bl1 = Bl[n * LDW + c0 + 4];
            #pragma unroll
            for (int mi = 0; mi < 2; mi++) {
                mma16bf(acc[mi][ni], ah[mi][0], ah[mi][1], ah[mi][2], ah[mi][3], bh0, bh1);
                mma16bf(acc[mi][ni], ah[mi][0], ah[mi][1], ah[mi][2], ah[mi][3], bl0, bl1);
                mma16bf(acc[mi][ni], al[mi][0], al[mi][1], al[mi][2], al[mi][3], bh0, bh1);
            }
        }
        // next iteration's head barrier orders reuse
    }

    #pragma unroll
    for (int mi = 0; mi < 2; mi++) {
        int r = by * 128 + wm * 32 + mi * 16 + r0;
        #pragma unroll
        for (int ni = 0; ni < 8; ni++) {
            int cc = bx * 128 + wn * 64 + ni * 8 + c0 * 2;
            float bb0 = bias ? bias[cc] : 0.f;
            float bb1 = bias ? bias[cc + 1] : 0.f;
            *(float2*)(C + (size_t)r * N + cc) =
                make_float2(acc[mi][ni][0] + bb0, acc[mi][ni][1] + bb1);
            *(float2*)(C + (size_t)(r + 8) * N + cc) =
                make_float2(acc[mi][ni][2] + bb0, acc[mi][ni][3] + bb1);
        }
    }
}

// ---------------------------------------------------------------------------
// tf32 flash attention (mainloop identical to R7; epilogue emits bf16 hi/lo)
// ---------------------------------------------------------------------------
#define LDK 76
#define LDV 72
#define LDP 68
#define KV_STG (64 * LDK + 64 * LDV)
#define ATTN_SMEM ((2 * KV_STG + 128 * LDP) * 4)
#define NTA (SEQ / 64)

__global__ __launch_bounds__(256, 2)
void attn_tf32(const float* __restrict__ qkv,
               uint16_t* __restrict__ atthi, uint16_t* __restrict__ attlo)
{
    extern __shared__ float smf[];
    uint32_t* Ps = (uint32_t*)(smf + 2 * KV_STG);

    const int tid  = threadIdx.x;
    const int lane = tid & 31;
    const int wid  = tid >> 5;
    const int b    = blockIdx.z;
    const int h    = blockIdx.y;
    const int qbase = blockIdx.x * 128 + wid * 16;
    const int r0 = lane >> 2;
    const int c0 = lane & 3;
    uint32_t* Pw = Ps + wid * 16 * LDP;

    auto stage_kv = [&](int kt, int buf) {
        float* Kd = smf + buf * KV_STG;
        float* Vd = Kd + 64 * LDK;
        #pragma unroll
        for (int i = 0; i < 4; i++) {
            int idx = tid + i * 256;
            int row = idx >> 4;
            int c4  = (idx & 15) * 4;
            const float* base = qkv + (size_t)(b * SEQ + kt * 64 + row) * QKV_N
                                + h * HDIM + c4;
            cpa16(Kd + row * LDK + c4, base + DIM);
            cpa16(Vd + row * LDV + c4, base + 2 * DIM);
        }
    };

    stage_kv(0, 0);
    CPA_COMMIT();

    uint32_t qa[8][4];
    {
        const float* qp = qkv + (size_t)(b * SEQ + qbase) * QKV_N + h * HDIM;
        #pragma unroll
        for (int ks = 0; ks < 8; ks++) {
            int d = ks * 8 + c0;
            qa[ks][0] = f2tf(0.125f * qp[(size_t)r0 * QKV_N + d]);
            qa[ks][1] = f2tf(0.125f * qp[(size_t)(r0 + 8) * QKV_N + d]);
            qa[ks][2] = f2tf(0.125f * qp[(size_t)r0 * QKV_N + d + 4]);
            qa[ks][3] = f2tf(0.125f * qp[(size_t)(r0 + 8) * QKV_N + d + 4]);
        }
    }

    float o[8][4];
    #pragma unroll
    for (int ni = 0; ni < 8; ni++)
        #pragma unroll
        for (int j = 0; j < 4; j++) o[ni][j] = 0.f;
    float m0 = -1e30f, m1 = -1e30f, l0 = 0.f, l1 = 0.f;

    CPA_WAIT(0);
    __syncthreads();

    for (int kt = 0; kt < NTA; kt++) {
        const int cur = kt & 1;
        if (kt + 1 < NTA) stage_kv(kt + 1, cur ^ 1);
        CPA_COMMIT();

        const float* Kc = smf + cur * KV_STG;
        const float* Vc = Kc + 64 * LDK;

        float s[8][4];
        #pragma unroll
        for (int ni = 0; ni < 8; ni++)
            #pragma unroll
            for (int j = 0; j < 4; j++) s[ni][j] = 0.f;

        #pragma unroll
        for (int ks = 0; ks < 8; ks++) {
            int d = ks * 8 + c0;
            #pragma unroll
            for (int ni = 0; ni < 8; ni++) {
                int kvr = ni * 8 + r0;
                uint32_t b0 = f2tf(Kc[kvr * LDK + d]);
                uint32_t b1 = f2tf(Kc[kvr * LDK + d + 4]);
                mma8(s[ni], qa[ks][0], qa[ks][1], qa[ks][2], qa[ks][3], b0, b1);
            }
        }

        float tm0 = -1e30f, tm1 = -1e30f;
        #pragma unroll
        for (int ni = 0; ni < 8; ni++) {
            tm0 = fmaxf(tm0, fmaxf(s[ni][0], s[ni][1]));
            tm1 = fmaxf(tm1, fmaxf(s[ni][2], s[ni][3]));
        }
        tm0 = fmaxf(tm0, __shfl_xor_sync(0xffffffffu, tm0, 1));
        tm0 = fmaxf(tm0, __shfl_xor_sync(0xffffffffu, tm0, 2));
        tm1 = fmaxf(tm1, __shfl_xor_sync(0xffffffffu, tm1, 1));
        tm1 = fmaxf(tm1, __shfl_xor_sync(0xffffffffu, tm1, 2));

        float nm0 = fmaxf(m0, tm0), nm1 = fmaxf(m1, tm1);
        float cor0 = __expf(m0 - nm0), cor1 = __expf(m1 - nm1);
        m0 = nm0; m1 = nm1;
        l0 *= cor0; l1 *= cor1;
        #pragma unroll
        for (int ni = 0; ni < 8; ni++) {
            o[ni][0] *= cor0; o[ni][1] *= cor0;
            o[ni][2] *= cor1; o[ni][3] *= cor1;
        }

        __syncwarp();
        #pragma unroll
        for (int ni = 0; ni < 8; ni++) {
            float p0 = __expf(s[ni][0] - nm0);
            float p1 = __expf(s[ni][1] - nm0);
            float p2 = __expf(s[ni][2] - nm1);
            float p3 = __expf(s[ni][3] - nm1);
            l0 += p0 + p1;
            l1 += p2 + p3;
            int col = ni * 8 + c0 * 2;
            *(uint2*)&Pw[r0 * LDP + col]       = make_uint2(f2tf(p0), f2tf(p1));
            *(uint2*)&Pw[(r0 + 8) * LDP + col] = make_uint2(f2tf(p2), f2tf(p3));
        }
        __syncwarp();

        #pragma unroll
        for (int ks = 0; ks < 8; ks++) {
            int kvl = ks * 8;
            uint32_t a0 = Pw[r0 * LDP + kvl + c0];
            uint32_t a1 = Pw[(r0 + 8) * LDP + kvl + c0];
            uint32_t a2 = Pw[r0 * LDP + kvl + c0 + 4];
            uint32_t a3 = Pw[(r0 + 8) * LDP + kvl + c0 + 4];
            #pragma unroll
            for (int ni = 0; ni < 8; ni++) {
                int d = ni * 8 + r0;
                uint32_t b0 = f2tf(Vc[(kvl + c0) * LDV + d]);
                uint32_t b1 = f2tf(Vc[(kvl + c0 + 4) * LDV + d]);
                mma8(o[ni], a0, a1, a2, a3, b0, b1);
            }
        }

        if (kt + 1 < NTA) {
            CPA_WAIT(0);
            __syncthreads();
        }
    }

    l0 += __shfl_xor_sync(0xffffffffu, l0, 1);
    l0 += __shfl_xor_sync(0xffffffffu, l0, 2);
    l1 += __shfl_xor_sync(0xffffffffu, l1, 1);
    l1 += __shfl_xor_sync(0xffffffffu, l1, 2);
    float inv0 = 1.f / l0, inv1 = 1.f / l1;

    // epilogue: write bf16 hi/lo pairs for proj GEMM (packed 2 per word)
    size_t rbase = (size_t)(b * SEQ + qbase) * DIM + h * HDIM;
    #pragma unroll
    for (int ni = 0; ni < 8; ni++) {
        int d = ni * 8 + c0 * 2;
        float v0 = o[ni][0] * inv0, v1 = o[ni][1] * inv0;
        float v2 = o[ni][2] * inv1, v3 = o[ni][3] * inv1;
        uint16_t h0 = f2bf(v0), h1 = f2bf(v1), h2 = f2bf(v2), h3 = f2bf(v3);
        uint16_t e0 = f2bf(v0 - bf2f(h0)), e1 = f2bf(v1 - bf2f(h1));
        uint16_t e2 = f2bf(v2 - bf2f(h2)), e3 = f2bf(v3 - bf2f(h3));
        size_t i0 = rbase + (size_t)r0 * DIM + d;
        size_t i1 = rbase + (size_t)(r0 + 8) * DIM + d;
        *(uint32_t*)&atthi[i0] = (uint32_t)h0 | ((uint32_t)h1 << 16);
        *(uint32_t*)&attlo[i0] = (uint32_t)e0 | ((uint32_t)e1 << 16);
        *(uint32_t*)&atthi[i1] = (uint32_t)h2 | ((uint32_t)h3 << 16);
        *(uint32_t*)&attlo[i1] = (uint32_t)e2 | ((uint32_t)e3 << 16);
    }
}

// ---------------------------------------------------------------------------
extern "C" void kernel_launch(void* const* d_in, const int* in_sizes, int n_in,
                              void* d_out, int out_size)
{
    const float* x      = (const float*)d_in[0];
    const float* w_qkv  = (const float*)d_in[1];
    const float* w_proj = (const float*)d_in[2];
    const float* b_proj = (const float*)d_in[3];
    float* out = (float*)d_out;

    float *qkv;
    uint16_t *xhi, *xlo, *wqh, *wql, *wph, *wpl, *athi, *atlo;
    cudaGetSymbolAddress((void**)&qkv,  g_qkv);
    cudaGetSymbolAddress((void**)&xhi,  g_xhi);
    cudaGetSymbolAddress((void**)&xlo,  g_xlo);
    cudaGetSymbolAddress((void**)&wqh,  g_wqkvhi);
    cudaGetSymbolAddress((void**)&wql,  g_wqkvlo);
    cudaGetSymbolAddress((void**)&wph,  g_wprojhi);
    cudaGetSymbolAddress((void**)&wpl,  g_wprojlo);
    cudaGetSymbolAddress((void**)&athi, g_atthi);
    cudaGetSymbolAddress((void**)&atlo, g_attlo);

    cudaFuncSetAttribute(gemm_bf16, cudaFuncAttributeMaxDynamicSharedMemorySize, GEMM_SMEM);
    cudaFuncSetAttribute(attn_tf32, cudaFuncAttributeMaxDynamicSharedMemorySize, ATTN_SMEM);

    // 0) pre-split inputs into bf16 hi/lo; transpose+split weights to [N][K]
    split_bf16<<<(M_TOT * DIM / 4 + 255) / 256, 256>>>(x, xhi, xlo, M_TOT * DIM / 4);
    tsplit_bf16<<<dim3(QKV_N / 32, DIM / 32), dim3(32, 8)>>>(w_qkv, wqh, wql, DIM, QKV_N);
    tsplit_bf16<<<dim3(DIM / 32, DIM / 32), dim3(32, 8)>>>(w_proj, wph, wpl, DIM, DIM);

    // 1) qkv = x @ w_qkv
    gemm_bf16<<<dim3(QKV_N / 128, M_TOT / 128), 256, GEMM_SMEM>>>(
        xhi, xlo, wqh, wql, nullptr, qkv, QKV_N, DIM);
    // 2) attention -> att (bf16 hi/lo)
    attn_tf32<<<dim3(SEQ / 128, HEADS, BATCH), 256, ATTN_SMEM>>>(qkv, athi, atlo);
    // 3) out = att @ w_proj + b
    gemm_bf16<<<dim3(DIM / 128, M_TOT / 128), 256, GEMM_SMEM>>>(
        athi, atlo, wph, wpl, b_proj, out, DIM, DIM);
}

// round 13
// speedup vs baseline: 4.0269x; 1.2411x over previous
#include <cuda_runtime.h>
#include <cuda_bf16.h>
#include <cuda_fp16.h>
#include <cstdint>

#define BATCH   4
#define SEQ     2048
#define DIM     768
#define HEADS   12
#define HDIM    64
#define M_TOT   8192
#define QKV_N   2304

// Scratch (device globals: allocation-guard-safe)
__device__ uint32_t g_q[(size_t)M_TOT * DIM];        // tf32 bits, pre-scaled by 1/8
__device__ uint32_t g_k[(size_t)M_TOT * DIM];        // tf32 bits
__device__ uint16_t g_vT[(size_t)BATCH * HEADS * HDIM * SEQ];  // fp16, [bh][d][n]
__device__ uint16_t g_xhi[(size_t)M_TOT * DIM];
__device__ uint16_t g_xlo[(size_t)M_TOT * DIM];
__device__ uint16_t g_wqkvhi[(size_t)QKV_N * DIM];   // TRANSPOSED [N][K]
__device__ uint16_t g_wqkvlo[(size_t)QKV_N * DIM];
__device__ uint16_t g_wprojhi[(size_t)DIM * DIM];
__device__ uint16_t g_wprojlo[(size_t)DIM * DIM];
__device__ uint16_t g_atthi[(size_t)M_TOT * DIM];
__device__ uint16_t g_attlo[(size_t)M_TOT * DIM];

// ---------------------------------------------------------------------------
__device__ __forceinline__ uint32_t f2tf(float x) {
    uint32_t u;
    asm("cvt.rna.tf32.f32 %0, %1;" : "=r"(u) : "f"(x));
    return u;
}
__device__ __forceinline__ uint16_t f2bf(float x) {
    return __bfloat16_as_ushort(__float2bfloat16_rn(x));
}
__device__ __forceinline__ float bf2f(uint16_t u) {
    return __bfloat162float(__ushort_as_bfloat16(u));
}
__device__ __forceinline__ uint16_t f2h(float x) {
    return __half_as_ushort(__float2half_rn(x));
}
__device__ __forceinline__ uint32_t pack_h2(float lo, float hi) {
    uint32_t r;
    asm("cvt.rn.f16x2.f32 %0, %1, %2;" : "=r"(r) : "f"(hi), "f"(lo));
    return r;
}

__device__ __forceinline__ void mma8(float* c,
                                     uint32_t a0, uint32_t a1, uint32_t a2, uint32_t a3,
                                     uint32_t b0, uint32_t b1) {
    asm volatile(
        "mma.sync.aligned.m16n8k8.row.col.f32.tf32.tf32.f32 "
        "{%0,%1,%2,%3},{%4,%5,%6,%7},{%8,%9},{%0,%1,%2,%3};"
        : "+f"(c[0]), "+f"(c[1]), "+f"(c[2]), "+f"(c[3])
        : "r"(a0), "r"(a1), "r"(a2), "r"(a3), "r"(b0), "r"(b1));
}
__device__ __forceinline__ void mma16bf(float* c,
                                        uint32_t a0, uint32_t a1, uint32_t a2, uint32_t a3,
                                        uint32_t b0, uint32_t b1) {
    asm volatile(
        "mma.sync.aligned.m16n8k16.row.col.f32.bf16.bf16.f32 "
        "{%0,%1,%2,%3},{%4,%5,%6,%7},{%8,%9},{%0,%1,%2,%3};"
        : "+f"(c[0]), "+f"(c[1]), "+f"(c[2]), "+f"(c[3])
        : "r"(a0), "r"(a1), "r"(a2), "r"(a3), "r"(b0), "r"(b1));
}
__device__ __forceinline__ void mma16h(float* c,
                                       uint32_t a0, uint32_t a1, uint32_t a2, uint32_t a3,
                                       uint32_t b0, uint32_t b1) {
    asm volatile(
        "mma.sync.aligned.m16n8k16.row.col.f32.f16.f16.f32 "
        "{%0,%1,%2,%3},{%4,%5,%6,%7},{%8,%9},{%0,%1,%2,%3};"
        : "+f"(c[0]), "+f"(c[1]), "+f"(c[2]), "+f"(c[3])
        : "r"(a0), "r"(a1), "r"(a2), "r"(a3), "r"(b0), "r"(b1));
}

__device__ __forceinline__ void cpa16(void* dst, const void* src) {
    uint32_t d = (uint32_t)__cvta_generic_to_shared(dst);
    asm volatile("cp.async.cg.shared.global [%0], [%1], 16;\n" :: "r"(d), "l"(src));
}
#define CPA_COMMIT()  asm volatile("cp.async.commit_group;\n" ::)
#define CPA_WAIT(n)   asm volatile("cp.async.wait_group %0;\n" :: "n"(n))

// ---------------------------------------------------------------------------
// Splitters
// ---------------------------------------------------------------------------
__global__ __launch_bounds__(256)
void split_bf16(const float* __restrict__ src, uint16_t* __restrict__ hi,
                uint16_t* __restrict__ lo, int n4)
{
    int i = blockIdx.x * 256 + threadIdx.x;
    if (i >= n4) return;
    float4 v = ((const float4*)src)[i];
    uint16_t h0 = f2bf(v.x), h1 = f2bf(v.y), h2 = f2bf(v.z), h3 = f2bf(v.w);
    uint16_t l0 = f2bf(v.x - bf2f(h0)), l1 = f2bf(v.y - bf2f(h1));
    uint16_t l2 = f2bf(v.z - bf2f(h2)), l3 = f2bf(v.w - bf2f(h3));
    ((uint2*)hi)[i] = make_uint2((uint32_t)h0 | ((uint32_t)h1 << 16),
                                 (uint32_t)h2 | ((uint32_t)h3 << 16));
    ((uint2*)lo)[i] = make_uint2((uint32_t)l0 | ((uint32_t)l1 << 16),
                                 (uint32_t)l2 | ((uint32_t)l3 << 16));
}

__global__ __launch_bounds__(256)
void tsplit_bf16(const float* __restrict__ in, uint16_t* __restrict__ hi,
                 uint16_t* __restrict__ lo, int K, int N)
{
    __shared__ float t[32][33];
    int n0 = blockIdx.x * 32, k0 = blockIdx.y * 32;
    #pragma unroll
    for (int i = threadIdx.y; i < 32; i += 8)
        t[i][threadIdx.x] = in[(size_t)(k0 + i) * N + n0 + threadIdx.x];
    __syncthreads();
    #pragma unroll
    for (int i = threadIdx.y; i < 32; i += 8) {
        float v = t[threadIdx.x][i];
        uint16_t h = f2bf(v);
        size_t o = (size_t)(n0 + i) * K + k0 + threadIdx.x;
        hi[o] = h;
        lo[o] = f2bf(v - bf2f(h));
    }
}

// ---------------------------------------------------------------------------
// 3xBF16 GEMM. BM=128 BN=128 BK=16, 256 thr. qkv_mode: epilogue writes
// Q (scaled tf32) / K (tf32) / V (fp16 transposed) planes instead of float C.
// ---------------------------------------------------------------------------
#define LDW  12
#define MATW (128 * LDW)
#define STGW (4 * MATW)
#define GEMM_SMEM (3 * STGW * 4)

__global__ __launch_bounds__(256, 2)
void gemm_bf16(const uint16_t* __restrict__ Ahi, const uint16_t* __restrict__ Alo,
               const uint16_t* __restrict__ Bhi, const uint16_t* __restrict__ Blo,
               const float* __restrict__ bias, float* __restrict__ C,
               uint32_t* __restrict__ Qd, uint32_t* __restrict__ Kd,
               uint16_t* __restrict__ Vt, int qkv_mode,
               int N, int K)
{
    extern __shared__ uint32_t gsm[];

    const int tid  = threadIdx.x;
    const int lane = tid & 31;
    const int wid  = tid >> 5;
    const int wm   = wid >> 1;
    const int wn   = wid & 1;
    const int r0   = lane >> 2;
    const int c0   = lane & 3;
    const int bx   = blockIdx.x;
    const int by   = blockIdx.y;
    const int nt   = K / 16;
    const int Kw   = K >> 1;

    const uint16_t* srcs[4] = {Ahi, Alo, Bhi, Blo};

    auto prefetch = [&](int t, int s) {
        uint32_t* st = gsm + s * STGW;
        #pragma unroll
        for (int i = 0; i < 4; i++) {
            int idx = tid + i * 256;
            int mat = idx >> 8;
            int r2  = idx & 255;
            int row = r2 >> 1;
            int ch  = r2 & 1;
            int rowbase = (mat < 2) ? by * 128 : bx * 128;
            const uint32_t* src = (const uint32_t*)srcs[mat]
                                  + (size_t)(rowbase + row) * Kw + t * 8 + ch * 4;
            cpa16(st + mat * MATW + row * LDW + ch * 4, src);
        }
    };

    float acc[2][8][4];
    #pragma unroll
    for (int mi = 0; mi < 2; mi++)
        #pragma unroll
        for (int ni = 0; ni < 8; ni++)
            #pragma unroll
            for (int j = 0; j < 4; j++) acc[mi][ni][j] = 0.f;

    prefetch(0, 0); CPA_COMMIT();
    prefetch(1, 1); CPA_COMMIT();

    for (int it = 0; it < nt; it++) {
        CPA_WAIT(1);
        __syncthreads();
        if (it + 2 < nt) prefetch(it + 2, (it + 2) % 3);
        CPA_COMMIT();

        const uint32_t* Ah = gsm + (it % 3) * STGW;
        const uint32_t* Al = Ah + MATW;
        const uint32_t* Bh = Al + MATW;
        const uint32_t* Bl = Bh + MATW;

        uint32_t ah[2][4], al[2][4];
        #pragma unroll
        for (int mi = 0; mi < 2; mi++) {
            int m = wm * 32 + mi * 16 + r0;
            ah[mi][0] = Ah[m * LDW + c0];
            ah[mi][1] = Ah[(m + 8) * LDW + c0];
            ah[mi][2] = Ah[m * LDW + c0 + 4];
            ah[mi][3] = Ah[(m + 8) * LDW + c0 + 4];
            al[mi][0] = Al[m * LDW + c0];
            al[mi][1] = Al[(m + 8) * LDW + c0];
            al[mi][2] = Al[m * LDW + c0 + 4];
            al[mi][3] = Al[(m + 8) * LDW + c0 + 4];
        }
        #pragma unroll
        for (int ni = 0; ni < 8; ni++) {
            int n = wn * 64 + ni * 8 + r0;
            uint32_t bh0 = Bh[n * LDW + c0];
            uint32_t bh1 = Bh[n * LDW + c0 + 4];
            uint32_t bl0 = Bl[n * LDW + c0];
            uint32_t bl1 = Bl[n * LDW + c0 + 4];
            #pragma unroll
            for (int mi = 0; mi < 2; mi++) {
                mma16bf(acc[mi][ni], ah[mi][0], ah[mi][1], ah[mi][2], ah[mi][3], bh0, bh1);
                mma16bf(acc[mi][ni], ah[mi][0], ah[mi][1], ah[mi][2], ah[mi][3], bl0, bl1);
                mma16bf(acc[mi][ni], al[mi][0], al[mi][1], al[mi][2], al[mi][3], bh0, bh1);
            }
        }
    }

    if (!qkv_mode) {
        #pragma unroll
        for (int mi = 0; mi < 2; mi++) {
            int r = by * 128 + wm * 32 + mi * 16 + r0;
            #pragma unroll
            for (int ni = 0; ni < 8; ni++) {
                int cc = bx * 128 + wn * 64 + ni * 8 + c0 * 2;
                float bb0 = bias ? bias[cc] : 0.f;
                float bb1 = bias ? bias[cc + 1] : 0.f;
                *(float2*)(C + (size_t)r * N + cc) =
                    make_float2(acc[mi][ni][0] + bb0, acc[mi][ni][1] + bb1);
                *(float2*)(C + (size_t)(r + 8) * N + cc) =
                    make_float2(acc[mi][ni][2] + bb0, acc[mi][ni][3] + bb1);
            }
        }
    } else {
        const int plane = (bx * 128) / DIM;     // 0=Q 1=K 2=V (tiles never straddle)
        #pragma unroll
        for (int mi = 0; mi < 2; mi++) {
            int r = by * 128 + wm * 32 + mi * 16 + r0;
            #pragma unroll
            for (int ni = 0; ni < 8; ni++) {
                int cc = bx * 128 + wn * 64 + ni * 8 + c0 * 2;
                if (plane == 0) {
                    int q = cc;
                    *(uint2*)(Qd + (size_t)r * DIM + q) =
                        make_uint2(f2tf(0.125f * acc[mi][ni][0]), f2tf(0.125f * acc[mi][ni][1]));
                    *(uint2*)(Qd + (size_t)(r + 8) * DIM + q) =
                        make_uint2(f2tf(0.125f * acc[mi][ni][2]), f2tf(0.125f * acc[mi][ni][3]));
                } else if (plane == 1) {
                    int q = cc - DIM;
                    *(uint2*)(Kd + (size_t)r * DIM + q) =
                        make_uint2(f2tf(acc[mi][ni][0]), f2tf(acc[mi][ni][1]));
                    *(uint2*)(Kd + (size_t)(r + 8) * DIM + q) =
                        make_uint2(f2tf(acc[mi][ni][2]), f2tf(acc[mi][ni][3]));
                } else {
                    int vc = cc - 2 * DIM;
                    int hh = vc >> 6, d = vc & 63;
                    int bb = r >> 11, n = r & 2047;
                    size_t base = ((size_t)(bb * HEADS + hh) * HDIM + d) * SEQ;
                    Vt[base + n]           = f2h(acc[mi][ni][0]);
                    Vt[base + SEQ + n]     = f2h(acc[mi][ni][1]);
                    Vt[base + n + 8]       = f2h(acc[mi][ni][2]);
                    Vt[base + SEQ + n + 8] = f2h(acc[mi][ni][3]);
                }
            }
        }
    }
}

// ---------------------------------------------------------------------------
// Flash attention: S = tf32 mma8 on pre-converted Q/K; PV = fp16 m16n8k16
// with in-register P packing (no P smem). V smem transposed [d][kv] fp16.
// ---------------------------------------------------------------------------
#define LDK  76
#define LDVT 36
#define K_TILE (64 * LDK)
#define V_TILE (64 * LDVT)
#define ATTN_SMEM ((2 * (K_TILE + V_TILE)) * 4)
#define NTA (SEQ / 64)

__global__ __launch_bounds__(256, 2)
void attn_flash(const uint32_t* __restrict__ Qd, const uint32_t* __restrict__ Kd,
                const uint16_t* __restrict__ Vt,
                uint16_t* __restrict__ atthi, uint16_t* __restrict__ attlo)
{
    extern __shared__ uint32_t smu[];
    uint32_t* Ksm = smu;                     // 2 x K tile (tf32)
    uint32_t* Vsm = smu + 2 * K_TILE;        // 2 x V tile (f16x2 words)

    const int tid  = threadIdx.x;
    const int lane = tid & 31;
    const int wid  = tid >> 5;
    const int b    = blockIdx.z;
    const int h    = blockIdx.y;
    const int qbase = blockIdx.x * 128 + wid * 16;
    const int r0 = lane >> 2;
    const int c0 = lane & 3;
    const size_t vbase = (size_t)(b * HEADS + h) * HDIM * SEQ;

    auto stage_k = [&](int kt, int buf) {
        uint32_t* Kdst = Ksm + buf * K_TILE;
        #pragma unroll
        for (int i = 0; i < 4; i++) {
            int idx = tid + i * 256;
            int row = idx >> 4;
            int c4  = (idx & 15) * 4;
            cpa16(Kdst + row * LDK + c4,
                  Kd + (size_t)(b * SEQ + kt * 64 + row) * DIM + h * HDIM + c4);
        }
    };
    auto stage_v = [&](int kt, int buf) {
        uint32_t* Vdst = Vsm + buf * V_TILE;
        #pragma unroll
        for (int i = 0; i < 2; i++) {
            int idx = tid + i * 256;         // 0..511
            int d   = idx >> 3;              // 0..63
            int ch  = idx & 7;               // 8 fp16 per chunk
            cpa16(Vdst + d * LDVT + ch * 4,
                  Vt + vbase + (size_t)d * SEQ + kt * 64 + ch * 8);
        }
    };

    stage_k(0, 0); stage_v(0, 0);
    CPA_COMMIT();

    // Q fragments: direct tf32-bit loads (already scaled by 1/8)
    uint32_t qa[8][4];
    {
        const uint32_t* qp = Qd + (size_t)(b * SEQ + qbase) * DIM + h * HDIM;
        #pragma unroll
        for (int ks = 0; ks < 8; ks++) {
            int d = ks * 8 + c0;
            qa[ks][0] = qp[(size_t)r0 * DIM + d];
            qa[ks][1] = qp[(size_t)(r0 + 8) * DIM + d];
            qa[ks][2] = qp[(size_t)r0 * DIM + d + 4];
            qa[ks][3] = qp[(size_t)(r0 + 8) * DIM + d + 4];
        }
    }

    float o[8][4];
    #pragma unroll
    for (int ni = 0; ni < 8; ni++)
        #pragma unroll
        for (int j = 0; j < 4; j++) o[ni][j] = 0.f;
    float m0 = -1e30f, m1 = -1e30f, l0 = 0.f, l1 = 0.f;

    CPA_WAIT(0);
    __syncthreads();

    for (int kt = 0; kt < NTA; kt++) {
        const int cur = kt & 1;
        if (kt + 1 < NTA) { stage_k(kt + 1, cur ^ 1); stage_v(kt + 1, cur ^ 1); }
        CPA_COMMIT();

        const uint32_t* Kc = Ksm + cur * K_TILE;
        const uint32_t* Vc = Vsm + cur * V_TILE;

        // S = Q K^T
        float s[8][4];
        #pragma unroll
        for (int ni = 0; ni < 8; ni++)
            #pragma unroll
            for (int j = 0; j < 4; j++) s[ni][j] = 0.f;

        #pragma unroll
        for (int ks = 0; ks < 8; ks++) {
            int d = ks * 8 + c0;
            #pragma unroll
            for (int ni = 0; ni < 8; ni++) {
                int kvr = ni * 8 + r0;
                mma8(s[ni], qa[ks][0], qa[ks][1], qa[ks][2], qa[ks][3],
                     Kc[kvr * LDK + d], Kc[kvr * LDK + d + 4]);
            }
        }

        // online softmax (p overwrites s in-place)
        float tm0 = -1e30f, tm1 = -1e30f;
        #pragma unroll
        for (int ni = 0; ni < 8; ni++) {
            tm0 = fmaxf(tm0, fmaxf(s[ni][0], s[ni][1]));
            tm1 = fmaxf(tm1, fmaxf(s[ni][2], s[ni][3]));
        }
        tm0 = fmaxf(tm0, __shfl_xor_sync(0xffffffffu, tm0, 1));
        tm0 = fmaxf(tm0, __shfl_xor_sync(0xffffffffu, tm0, 2));
        tm1 = fmaxf(tm1, __shfl_xor_sync(0xffffffffu, tm1, 1));
        tm1 = fmaxf(tm1, __shfl_xor_sync(0xffffffffu, tm1, 2));

        float nm0 = fmaxf(m0, tm0), nm1 = fmaxf(m1, tm1);
        float cor0 = __expf(m0 - nm0), cor1 = __expf(m1 - nm1);
        m0 = nm0; m1 = nm1;
        l0 *= cor0; l1 *= cor1;
        #pragma unroll
        for (int ni = 0; ni < 8; ni++) {
            o[ni][0] *= cor0; o[ni][1] *= cor0;
            o[ni][2] *= cor1; o[ni][3] *= cor1;
        }
        #pragma unroll
        for (int ni = 0; ni < 8; ni++) {
            s[ni][0] = __expf(s[ni][0] - nm0);
            s[ni][1] = __expf(s[ni][1] - nm0);
            s[ni][2] = __expf(s[ni][2] - nm1);
            s[ni][3] = __expf(s[ni][3] - nm1);
            l0 += s[ni][0] + s[ni][1];
            l1 += s[ni][2] + s[ni][3];
        }

        // O += P V : fp16 m16n8k16, P packed in registers (no smem)
        #pragma unroll
        for (int j = 0; j < 4; j++) {
            uint32_t a0 = pack_h2(s[2 * j][0],     s[2 * j][1]);
            uint32_t a1 = pack_h2(s[2 * j][2],     s[2 * j][3]);
            uint32_t a2 = pack_h2(s[2 * j + 1][0], s[2 * j + 1][1]);
            uint32_t a3 = pack_h2(s[2 * j + 1][2], s[2 * j + 1][3]);
            #pragma unroll
            for (int nd = 0; nd < 8; nd++) {
                const uint32_t* vr = Vc + (nd * 8 + r0) * LDVT + 8 * j + c0;
                mma16h(o[nd], a0, a1, a2, a3, vr[0], vr[4]);
            }
        }

        if (kt + 1 < NTA) {
            CPA_WAIT(0);
            __syncthreads();
        }
    }

    l0 += __shfl_xor_sync(0xffffffffu, l0, 1);
    l0 += __shfl_xor_sync(0xffffffffu, l0, 2);
    l1 += __shfl_xor_sync(0xffffffffu, l1, 1);
    l1 += __shfl_xor_sync(0xffffffffu, l1, 2);
    float inv0 = 1.f / l0, inv1 = 1.f / l1;

    // epilogue: bf16 hi/lo for proj GEMM
    size_t rbase = (size_t)(b * SEQ + qbase) * DIM + h * HDIM;
    #pragma unroll
    for (int ni = 0; ni < 8; ni++) {
        int d = ni * 8 + c0 * 2;
        float v0 = o[ni][0] * inv0, v1 = o[ni][1] * inv0;
        float v2 = o[ni][2] * inv1, v3 = o[ni][3] * inv1;
        uint16_t h0 = f2bf(v0), h1 = f2bf(v1), h2 = f2bf(v2), h3 = f2bf(v3);
        uint16_t e0 = f2bf(v0 - bf2f(h0)), e1 = f2bf(v1 - bf2f(h1));
        uint16_t e2 = f2bf(v2 - bf2f(h2)), e3 = f2bf(v3 - bf2f(h3));
        size_t i0 = rbase + (size_t)r0 * DIM + d;
        size_t i1 = rbase + (size_t)(r0 + 8) * DIM + d;
        *(uint32_t*)&atthi[i0] = (uint32_t)h0 | ((uint32_t)h1 << 16);
        *(uint32_t*)&attlo[i0] = (uint32_t)e0 | ((uint32_t)e1 << 16);
        *(uint32_t*)&atthi[i1] = (uint32_t)h2 | ((uint32_t)h3 << 16);
        *(uint32_t*)&attlo[i1] = (uint32_t)e2 | ((uint32_t)e3 << 16);
    }
}

// ---------------------------------------------------------------------------
extern "C" void kernel_launch(void* const* d_in, const int* in_sizes, int n_in,
                              void* d_out, int out_size)
{
    const float* x      = (const float*)d_in[0];
    const float* w_qkv  = (const float*)d_in[1];
    const float* w_proj = (const float*)d_in[2];
    const float* b_proj = (const float*)d_in[3];
    float* out = (float*)d_out;

    uint32_t *qd, *kd;
    uint16_t *vt, *xhi, *xlo, *wqh, *wql, *wph, *wpl, *athi, *atlo;
    cudaGetSymbolAddress((void**)&qd,   g_q);
    cudaGetSymbolAddress((void**)&kd,   g_k);
    cudaGetSymbolAddress((void**)&vt,   g_vT);
    cudaGetSymbolAddress((void**)&xhi,  g_xhi);
    cudaGetSymbolAddress((void**)&xlo,  g_xlo);
    cudaGetSymbolAddress((void**)&wqh,  g_wqkvhi);
    cudaGetSymbolAddress((void**)&wql,  g_wqkvlo);
    cudaGetSymbolAddress((void**)&wph,  g_wprojhi);
    cudaGetSymbolAddress((void**)&wpl,  g_wprojlo);
    cudaGetSymbolAddress((void**)&athi, g_atthi);
    cudaGetSymbolAddress((void**)&atlo, g_attlo);

    cudaFuncSetAttribute(gemm_bf16, cudaFuncAttributeMaxDynamicSharedMemorySize, GEMM_SMEM);
    cudaFuncSetAttribute(attn_flash, cudaFuncAttributeMaxDynamicSharedMemorySize, ATTN_SMEM);

    split_bf16<<<(M_TOT * DIM / 4 + 255) / 256, 256>>>(x, xhi, xlo, M_TOT * DIM / 4);
    tsplit_bf16<<<dim3(QKV_N / 32, DIM / 32), dim3(32, 8)>>>(w_qkv, wqh, wql, DIM, QKV_N);
    tsplit_bf16<<<dim3(DIM / 32, DIM / 32), dim3(32, 8)>>>(w_proj, wph, wpl, DIM, DIM);

    // 1) qkv GEMM -> pre-converted Q/K (tf32) + transposed V (fp16)
    gemm_bf16<<<dim3(QKV_N / 128, M_TOT / 128), 256, GEMM_SMEM>>>(
        xhi, xlo, wqh, wql, nullptr, nullptr, qd, kd, vt, 1, QKV_N, DIM);
    // 2) attention
    attn_flash<<<dim3(SEQ / 128, HEADS, BATCH), 256, ATTN_SMEM>>>(qd, kd, vt, athi, atlo);
    // 3) out = att @ w_proj + b
    gemm_bf16<<<dim3(DIM / 128, M_TOT / 128), 256, GEMM_SMEM>>>(
        athi, atlo, wph, wpl, b_proj, out, nullptr, nullptr, nullptr, 0, DIM, DIM);
}

// round 16
// speedup vs baseline: 6.2124x; 1.5427x over previous
#include <cuda_runtime.h>
#include <cuda_bf16.h>
#include <cuda_fp16.h>
#include <cstdint>

#define BATCH   4
#define SEQ     2048
#define DIM     768
#define HEADS   12
#define HDIM    64
#define M_TOT   8192
#define QKV_N   2304

// Scratch (device globals: allocation-guard-safe)
__device__ uint32_t g_q[(size_t)M_TOT * DIM];        // tf32 bits, pre-scaled by 1/8
__device__ uint32_t g_k[(size_t)M_TOT * DIM];        // tf32 bits
__device__ uint16_t g_vT[(size_t)BATCH * HEADS * HDIM * SEQ];  // fp16, [bh][d][n]
__device__ uint16_t g_xh[(size_t)M_TOT * DIM];       // fp16 [M][K]
__device__ uint16_t g_wqkvh[(size_t)QKV_N * DIM];    // fp16 TRANSPOSED [N][K]
__device__ uint16_t g_wprojh[(size_t)DIM * DIM];     // fp16 TRANSPOSED [N][K]
__device__ uint16_t g_atth[(size_t)M_TOT * DIM];     // fp16 [M][K]

// ---------------------------------------------------------------------------
__device__ __forceinline__ uint32_t f2tf(float x) {
    uint32_t u;
    asm("cvt.rna.tf32.f32 %0, %1;" : "=r"(u) : "f"(x));
    return u;
}
__device__ __forceinline__ uint16_t f2h(float x) {
    return __half_as_ushort(__float2half_rn(x));
}
__device__ __forceinline__ uint32_t pack_h2(float lo, float hi) {
    uint32_t r;
    asm("cvt.rn.f16x2.f32 %0, %1, %2;" : "=r"(r) : "f"(hi), "f"(lo));
    return r;
}

__device__ __forceinline__ void mma8(float* c,
                                     uint32_t a0, uint32_t a1, uint32_t a2, uint32_t a3,
                                     uint32_t b0, uint32_t b1) {
    asm volatile(
        "mma.sync.aligned.m16n8k8.row.col.f32.tf32.tf32.f32 "
        "{%0,%1,%2,%3},{%4,%5,%6,%7},{%8,%9},{%0,%1,%2,%3};"
        : "+f"(c[0]), "+f"(c[1]), "+f"(c[2]), "+f"(c[3])
        : "r"(a0), "r"(a1), "r"(a2), "r"(a3), "r"(b0), "r"(b1));
}
__device__ __forceinline__ void mma16h(float* c,
                                       uint32_t a0, uint32_t a1, uint32_t a2, uint32_t a3,
                                       uint32_t b0, uint32_t b1) {
    asm volatile(
        "mma.sync.aligned.m16n8k16.row.col.f32.f16.f16.f32 "
        "{%0,%1,%2,%3},{%4,%5,%6,%7},{%8,%9},{%0,%1,%2,%3};"
        : "+f"(c[0]), "+f"(c[1]), "+f"(c[2]), "+f"(c[3])
        : "r"(a0), "r"(a1), "r"(a2), "r"(a3), "r"(b0), "r"(b1));
}

__device__ __forceinline__ void cpa16(void* dst, const void* src) {
    uint32_t d = (uint32_t)__cvta_generic_to_shared(dst);
    asm volatile("cp.async.cg.shared.global [%0], [%1], 16;\n" :: "r"(d), "l"(src));
}
#define CPA_COMMIT()  asm volatile("cp.async.commit_group;\n" ::)
#define CPA_WAIT(n)   asm volatile("cp.async.wait_group %0;\n" :: "n"(n))

// ---------------------------------------------------------------------------
// Converters: fp32 -> fp16
// ---------------------------------------------------------------------------
__global__ __launch_bounds__(256)
void conv_h(const float* __restrict__ src, uint16_t* __restrict__ dst, int n4)
{
    int i = blockIdx.x * 256 + threadIdx.x;
    if (i >= n4) return;
    float4 v = ((const float4*)src)[i];
    ((uint2*)dst)[i] = make_uint2(pack_h2(v.x, v.y), pack_h2(v.z, v.w));
}

// transpose + convert: in[K][N] -> fp16 [N][K]
__global__ __launch_bounds__(256)
void tconv_h(const float* __restrict__ in, uint16_t* __restrict__ dst, int K, int N)
{
    __shared__ float t[32][33];
    int n0 = blockIdx.x * 32, k0 = blockIdx.y * 32;
    #pragma unroll
    for (int i = threadIdx.y; i < 32; i += 8)
        t[i][threadIdx.x] = in[(size_t)(k0 + i) * N + n0 + threadIdx.x];
    __syncthreads();
    #pragma unroll
    for (int i = threadIdx.y; i < 32; i += 8) {
        float v = t[threadIdx.x][i];
        dst[(size_t)(n0 + i) * K + k0 + threadIdx.x] = f2h(v);
    }
}

// ---------------------------------------------------------------------------
// Plain fp16 GEMM. BM=128 BN=128 BK=32, 256 thr, 8 warps (4x2), warp 32x64.
// A [M][K] fp16; B [N][K] fp16 (pre-transposed). 3-stage cp.async pipeline.
// smem rows: 16 data words (k-pairs) + 4 pad -> LDW=20, conflict-free frags.
// qkv_mode: epilogue writes Q(tf32,scaled)/K(tf32)/V(fp16,transposed) planes.
// ---------------------------------------------------------------------------
#define LDW  20
#define MATW (128 * LDW)
#define STGW (2 * MATW)
#define GEMM_SMEM (3 * STGW * 4)

__global__ __launch_bounds__(256, 2)
void gemm_h(const uint16_t* __restrict__ Ah, const uint16_t* __restrict__ Bh,
            const float* __restrict__ bias, float* __restrict__ C,
            uint32_t* __restrict__ Qd, uint32_t* __restrict__ Kd,
            uint16_t* __restrict__ Vt, int qkv_mode,
            int N, int K)
{
    extern __shared__ uint32_t gsm[];

    const int tid  = threadIdx.x;
    const int lane = tid & 31;
    const int wid  = tid >> 5;
    const int wm   = wid >> 1;
    const int wn   = wid & 1;
    const int r0   = lane >> 2;
    const int c0   = lane & 3;
    const int bx   = blockIdx.x;
    const int by   = blockIdx.y;
    const int nt   = K / 32;
    const int Kw   = K >> 1;          // K in fp16-pair words

    auto prefetch = [&](int t, int s) {
        uint32_t* st = gsm + s * STGW;
        #pragma unroll
        for (int i = 0; i < 4; i++) {
            int idx = tid + i * 256;            // 0..1023
            int mat = idx >> 9;                 // 0..1
            int r2  = idx & 511;
            int row = r2 >> 2;                  // 0..127
            int ch  = r2 & 3;                   // 16B chunk (4 words)
            const uint16_t* S = mat ? Bh : Ah;
            int rowbase = mat ? bx * 128 : by * 128;
            const uint32_t* src = (const uint32_t*)S
                                  + (size_t)(rowbase + row) * Kw + t * 16 + ch * 4;
            cpa16(st + mat * MATW + row * LDW + ch * 4, src);
        }
    };

    float acc[2][8][4];
    #pragma unroll
    for (int mi = 0; mi < 2; mi++)
        #pragma unroll
        for (int ni = 0; ni < 8; ni++)
            #pragma unroll
            for (int j = 0; j < 4; j++) acc[mi][ni][j] = 0.f;

    prefetch(0, 0); CPA_COMMIT();
    prefetch(1, 1); CPA_COMMIT();

    for (int it = 0; it < nt; it++) {
        CPA_WAIT(1);
        __syncthreads();
        if (it + 2 < nt) prefetch(it + 2, (it + 2) % 3);
        CPA_COMMIT();

        const uint32_t* As = gsm + (it % 3) * STGW;
        const uint32_t* Bs = As + MATW;

        #pragma unroll
        for (int kc = 0; kc < 2; kc++) {
            const int kw = kc * 8 + c0;
            uint32_t a[2][4];
            #pragma unroll
            for (int mi = 0; mi < 2; mi++) {
                int m = wm * 32 + mi * 16 + r0;
                a[mi][0] = As[m * LDW + kw];
                a[mi][1] = As[(m + 8) * LDW + kw];
                a[mi][2] = As[m * LDW + kw + 4];
                a[mi][3] = As[(m + 8) * LDW + kw + 4];
            }
            #pragma unroll
            for (int ni = 0; ni < 8; ni++) {
                int n = wn * 64 + ni * 8 + r0;
                uint32_t b0 = Bs[n * LDW + kw];
                uint32_t b1 = Bs[n * LDW + kw + 4];
                #pragma unroll
                for (int mi = 0; mi < 2; mi++)
                    mma16h(acc[mi][ni], a[mi][0], a[mi][1], a[mi][2], a[mi][3], b0, b1);
            }
        }
    }

    if (!qkv_mode) {
        #pragma unroll
        for (int mi = 0; mi < 2; mi++) {
            int r = by * 128 + wm * 32 + mi * 16 + r0;
            #pragma unroll
            for (int ni = 0; ni < 8; ni++) {
                int cc = bx * 128 + wn * 64 + ni * 8 + c0 * 2;
                float bb0 = bias ? bias[cc] : 0.f;
                float bb1 = bias ? bias[cc + 1] : 0.f;
                *(float2*)(C + (size_t)r * N + cc) =
                    make_float2(acc[mi][ni][0] + bb0, acc[mi][ni][1] + bb1);
                *(float2*)(C + (size_t)(r + 8) * N + cc) =
                    make_float2(acc[mi][ni][2] + bb0, acc[mi][ni][3] + bb1);
            }
        }
    } else {
        const int plane = (bx * 128) / DIM;     // 0=Q 1=K 2=V (tiles never straddle)
        #pragma unroll
        for (int mi = 0; mi < 2; mi++) {
            int r = by * 128 + wm * 32 + mi * 16 + r0;
            #pragma unroll
            for (int ni = 0; ni < 8; ni++) {
                int cc = bx * 128 + wn * 64 + ni * 8 + c0 * 2;
                if (plane == 0) {
                    int q = cc;
                    *(uint2*)(Qd + (size_t)r * DIM + q) =
                        make_uint2(f2tf(0.125f * acc[mi][ni][0]), f2tf(0.125f * acc[mi][ni][1]));
                    *(uint2*)(Qd + (size_t)(r + 8) * DIM + q) =
                        make_uint2(f2tf(0.125f * acc[mi][ni][2]), f2tf(0.125f * acc[mi][ni][3]));
                } else if (plane == 1) {
                    int q = cc - DIM;
                    *(uint2*)(Kd + (size_t)r * DIM + q) =
                        make_uint2(f2tf(acc[mi][ni][0]), f2tf(acc[mi][ni][1]));
                    *(uint2*)(Kd + (size_t)(r + 8) * DIM + q) =
                        make_uint2(f2tf(acc[mi][ni][2]), f2tf(acc[mi][ni][3]));
                } else {
                    int vc = cc - 2 * DIM;
                    int hh = vc >> 6, d = vc & 63;
                    int bb = r >> 11, n = r & 2047;
                    size_t base = ((size_t)(bb * HEADS + hh) * HDIM + d) * SEQ;
                    Vt[base + n]           = f2h(acc[mi][ni][0]);
                    Vt[base + SEQ + n]     = f2h(acc[mi][ni][1]);
                    Vt[base + n + 8]       = f2h(acc[mi][ni][2]);
                    Vt[base + SEQ + n + 8] = f2h(acc[mi][ni][3]);
                }
            }
        }
    }
}

// ---------------------------------------------------------------------------
// Flash attention: S = tf32 mma8 on pre-converted Q/K; PV = fp16 m16n8k16
// with in-register P packing (no P smem). V smem transposed [d][kv] fp16.
// ---------------------------------------------------------------------------
#define LDK  76
#define LDVT 36
#define K_TILE (64 * LDK)
#define V_TILE (64 * LDVT)
#define ATTN_SMEM ((2 * (K_TILE + V_TILE)) * 4)
#define NTA (SEQ / 64)

__global__ __launch_bounds__(256, 2)
void attn_flash(const uint32_t* __restrict__ Qd, const uint32_t* __restrict__ Kd,
                const uint16_t* __restrict__ Vt, uint16_t* __restrict__ atth)
{
    extern __shared__ uint32_t smu[];
    uint32_t* Ksm = smu;                     // 2 x K tile (tf32)
    uint32_t* Vsm = smu + 2 * K_TILE;        // 2 x V tile (f16x2 words)

    const int tid  = threadIdx.x;
    const int lane = tid & 31;
    const int wid  = tid >> 5;
    const int b    = blockIdx.z;
    const int h    = blockIdx.y;
    const int qbase = blockIdx.x * 128 + wid * 16;
    const int r0 = lane >> 2;
    const int c0 = lane & 3;
    const size_t vbase = (size_t)(b * HEADS + h) * HDIM * SEQ;

    auto stage_k = [&](int kt, int buf) {
        uint32_t* Kdst = Ksm + buf * K_TILE;
        #pragma unroll
        for (int i = 0; i < 4; i++) {
            int idx = tid + i * 256;
            int row = idx >> 4;
            int c4  = (idx & 15) * 4;
            cpa16(Kdst + row * LDK + c4,
                  Kd + (size_t)(b * SEQ + kt * 64 + row) * DIM + h * HDIM + c4);
        }
    };
    auto stage_v = [&](int kt, int buf) {
        uint32_t* Vdst = Vsm + buf * V_TILE;
        #pragma unroll
        for (int i = 0; i < 2; i++) {
            int idx = tid + i * 256;         // 0..511
            int d   = idx >> 3;              // 0..63
            int ch  = idx & 7;               // 8 fp16 per chunk
            cpa16(Vdst + d * LDVT + ch * 4,
                  Vt + vbase + (size_t)d * SEQ + kt * 64 + ch * 8);
        }
    };

    stage_k(0, 0); stage_v(0, 0);
    CPA_COMMIT();

    // Q fragments: direct tf32-bit loads (already scaled by 1/8)
    uint32_t qa[8][4];
    {
        const uint32_t* qp = Qd + (size_t)(b * SEQ + qbase) * DIM + h * HDIM;
        #pragma unroll
        for (int ks = 0; ks < 8; ks++) {
            int d = ks * 8 + c0;
            qa[ks][0] = qp[(size_t)r0 * DIM + d];
            qa[ks][1] = qp[(size_t)(r0 + 8) * DIM + d];
            qa[ks][2] = qp[(size_t)r0 * DIM + d + 4];
            qa[ks][3] = qp[(size_t)(r0 + 8) * DIM + d + 4];
        }
    }

    float o[8][4];
    #pragma unroll
    for (int ni = 0; ni < 8; ni++)
        #pragma unroll
        for (int j = 0; j < 4; j++) o[ni][j] = 0.f;
    float m0 = -1e30f, m1 = -1e30f, l0 = 0.f, l1 = 0.f;

    CPA_WAIT(0);
    __syncthreads();

    for (int kt = 0; kt < NTA; kt++) {
        const int cur = kt & 1;
        if (kt + 1 < NTA) { stage_k(kt + 1, cur ^ 1); stage_v(kt + 1, cur ^ 1); }
        CPA_COMMIT();

        const uint32_t* Kc = Ksm + cur * K_TILE;
        const uint32_t* Vc = Vsm + cur * V_TILE;

        // S = Q K^T
        float s[8][4];
        #pragma unroll
        for (int ni = 0; ni < 8; ni++)
            #pragma unroll
            for (int j = 0; j < 4; j++) s[ni][j] = 0.f;

        #pragma unroll
        for (int ks = 0; ks < 8; ks++) {
            int d = ks * 8 + c0;
            #pragma unroll
            for (int ni = 0; ni < 8; ni++) {
                int kvr = ni * 8 + r0;
                mma8(s[ni], qa[ks][0], qa[ks][1], qa[ks][2], qa[ks][3],
                     Kc[kvr * LDK + d], Kc[kvr * LDK + d + 4]);
            }
        }

        // online softmax (p overwrites s in-place)
        float tm0 = -1e30f, tm1 = -1e30f;
        #pragma unroll
        for (int ni = 0; ni < 8; ni++) {
            tm0 = fmaxf(tm0, fmaxf(s[ni][0], s[ni][1]));
            tm1 = fmaxf(tm1, fmaxf(s[ni][2], s[ni][3]));
        }
        tm0 = fmaxf(tm0, __shfl_xor_sync(0xffffffffu, tm0, 1));
        tm0 = fmaxf(tm0, __shfl_xor_sync(0xffffffffu, tm0, 2));
        tm1 = fmaxf(tm1, __shfl_xor_sync(0xffffffffu, tm1, 1));
        tm1 = fmaxf(tm1, __shfl_xor_sync(0xffffffffu, tm1, 2));

        float nm0 = fmaxf(m0, tm0), nm1 = fmaxf(m1, tm1);
        float cor0 = __expf(m0 - nm0), cor1 = __expf(m1 - nm1);
        m0 = nm0; m1 = nm1;
        l0 *= cor0; l1 *= cor1;
        #pragma unroll
        for (int ni = 0; ni < 8; ni++) {
            o[ni][0] *= cor0; o[ni][1] *= cor0;
            o[ni][2] *= cor1; o[ni][3] *= cor1;
        }
        #pragma unroll
        for (int ni = 0; ni < 8; ni++) {
            s[ni][0] = __expf(s[ni][0] - nm0);
            s[ni][1] = __expf(s[ni][1] - nm0);
            s[ni][2] = __expf(s[ni][2] - nm1);
            s[ni][3] = __expf(s[ni][3] - nm1);
            l0 += s[ni][0] + s[ni][1];
            l1 += s[ni][2] + s[ni][3];
        }

        // O += P V : fp16 m16n8k16, P packed in registers (no smem)
        #pragma unroll
        for (int j = 0; j < 4; j++) {
            uint32_t a0 = pack_h2(s[2 * j][0],     s[2 * j][1]);
            uint32_t a1 = pack_h2(s[2 * j][2],     s[2 * j][3]);
            uint32_t a2 = pack_h2(s[2 * j + 1][0], s[2 * j + 1][1]);
            uint32_t a3 = pack_h2(s[2 * j + 1][2], s[2 * j + 1][3]);
            #pragma unroll
            for (int nd = 0; nd < 8; nd++) {
                const uint32_t* vr = Vc + (nd * 8 + r0) * LDVT + 8 * j + c0;
                mma16h(o[nd], a0, a1, a2, a3, vr[0], vr[4]);
            }
        }

        if (kt + 1 < NTA) {
            CPA_WAIT(0);
            __syncthreads();
        }
    }

    l0 += __shfl_xor_sync(0xffffffffu, l0, 1);
    l0 += __shfl_xor_sync(0xffffffffu, l0, 2);
    l1 += __shfl_xor_sync(0xffffffffu, l1, 1);
    l1 += __shfl_xor_sync(0xffffffffu, l1, 2);
    float inv0 = 1.f / l0, inv1 = 1.f / l1;

    // epilogue: fp16 att for proj GEMM
    size_t rbase = (size_t)(b * SEQ + qbase) * DIM + h * HDIM;
    #pragma unroll
    for (int ni = 0; ni < 8; ni++) {
        int d = ni * 8 + c0 * 2;
        size_t i0 = rbase + (size_t)r0 * DIM + d;
        size_t i1 = rbase + (size_t)(r0 + 8) * DIM + d;
        *(uint32_t*)&atth[i0] = pack_h2(o[ni][0] * inv0, o[ni][1] * inv0);
        *(uint32_t*)&atth[i1] = pack_h2(o[ni][2] * inv1, o[ni][3] * inv1);
    }
}

// ---------------------------------------------------------------------------
extern "C" void kernel_launch(void* const* d_in, const int* in_sizes, int n_in,
                              void* d_out, int out_size)
{
    const float* x      = (const float*)d_in[0];
    const float* w_qkv  = (const float*)d_in[1];
    const float* w_proj = (const float*)d_in[2];
    const float* b_proj = (const float*)d_in[3];
    float* out = (float*)d_out;

    uint32_t *qd, *kd;
    uint16_t *vt, *xh, *wqh, *wph, *ath;
    cudaGetSymbolAddress((void**)&qd,  g_q);
    cudaGetSymbolAddress((void**)&kd,  g_k);
    cudaGetSymbolAddress((void**)&vt,  g_vT);
    cudaGetSymbolAddress((void**)&xh,  g_xh);
    cudaGetSymbolAddress((void**)&wqh, g_wqkvh);
    cudaGetSymbolAddress((void**)&wph, g_wprojh);
    cudaGetSymbolAddress((void**)&ath, g_atth);

    cudaFuncSetAttribute(gemm_h, cudaFuncAttributeMaxDynamicSharedMemorySize, GEMM_SMEM);
    cudaFuncSetAttribute(attn_flash, cudaFuncAttributeMaxDynamicSharedMemorySize, ATTN_SMEM);

    // 0) convert inputs to fp16 (weights transposed to [N][K])
    conv_h<<<(M_TOT * DIM / 4 + 255) / 256, 256>>>(x, xh, M_TOT * DIM / 4);
    tconv_h<<<dim3(QKV_N / 32, DIM / 32), dim3(32, 8)>>>(w_qkv, wqh, DIM, QKV_N);
    tconv_h<<<dim3(DIM / 32, DIM / 32), dim3(32, 8)>>>(w_proj, wph, DIM, DIM);

    // 1) qkv GEMM -> pre-converted Q/K (tf32) + transposed V (fp16)
    gemm_h<<<dim3(QKV_N / 128, M_TOT / 128), 256, GEMM_SMEM>>>(
        xh, wqh, nullptr, nullptr, qd, kd, vt, 1, QKV_N, DIM);
    // 2) attention -> att (fp16)
    attn_flash<<<dim3(SEQ / 128, HEADS, BATCH), 256, ATTN_SMEM>>>(qd, kd, vt, ath);
    // 3) out = att @ w_proj + b
    gemm_h<<<dim3(DIM / 128, M_TOT / 128), 256, GEMM_SMEM>>>(
        ath, wph, b_proj, out, nullptr, nullptr, nullptr, 0, DIM, DIM);
}

// round 17
// speedup vs baseline: 7.7218x; 1.2430x over previous
#include <cuda_runtime.h>
#include <cuda_bf16.h>
#include <cuda_fp16.h>
#include <cstdint>

#define BATCH   4
#define SEQ     2048
#define DIM     768
#define HEADS   12
#define HDIM    64
#define M_TOT   8192
#define QKV_N   2304

// Scratch (device globals: allocation-guard-safe)
__device__ uint16_t g_qh[(size_t)M_TOT * DIM];       // fp16, pre-scaled by 1/8, [M][DIM]
__device__ uint16_t g_kh[(size_t)M_TOT * DIM];       // fp16, [M][DIM]
__device__ uint16_t g_vT[(size_t)BATCH * HEADS * HDIM * SEQ];  // fp16, [bh][d][n]
__device__ uint16_t g_xh[(size_t)M_TOT * DIM];       // fp16 [M][K]
__device__ uint16_t g_wqkvh[(size_t)QKV_N * DIM];    // fp16 TRANSPOSED [N][K]
__device__ uint16_t g_wprojh[(size_t)DIM * DIM];     // fp16 TRANSPOSED [N][K]
__device__ uint16_t g_atth[(size_t)M_TOT * DIM];     // fp16 [M][K]

// ---------------------------------------------------------------------------
__device__ __forceinline__ uint16_t f2h(float x) {
    return __half_as_ushort(__float2half_rn(x));
}
__device__ __forceinline__ uint32_t pack_h2(float lo, float hi) {
    uint32_t r;
    asm("cvt.rn.f16x2.f32 %0, %1, %2;" : "=r"(r) : "f"(hi), "f"(lo));
    return r;
}

__device__ __forceinline__ void mma16h(float* c,
                                       uint32_t a0, uint32_t a1, uint32_t a2, uint32_t a3,
                                       uint32_t b0, uint32_t b1) {
    asm volatile(
        "mma.sync.aligned.m16n8k16.row.col.f32.f16.f16.f32 "
        "{%0,%1,%2,%3},{%4,%5,%6,%7},{%8,%9},{%0,%1,%2,%3};"
        : "+f"(c[0]), "+f"(c[1]), "+f"(c[2]), "+f"(c[3])
        : "r"(a0), "r"(a1), "r"(a2), "r"(a3), "r"(b0), "r"(b1));
}

__device__ __forceinline__ void cpa16(void* dst, const void* src) {
    uint32_t d = (uint32_t)__cvta_generic_to_shared(dst);
    asm volatile("cp.async.cg.shared.global [%0], [%1], 16;\n" :: "r"(d), "l"(src));
}
#define CPA_COMMIT()  asm volatile("cp.async.commit_group;\n" ::)
#define CPA_WAIT(n)   asm volatile("cp.async.wait_group %0;\n" :: "n"(n))

// ---------------------------------------------------------------------------
// Converters: fp32 -> fp16
// ---------------------------------------------------------------------------
__global__ __launch_bounds__(256)
void conv_h(const float* __restrict__ src, uint16_t* __restrict__ dst, int n4)
{
    int i = blockIdx.x * 256 + threadIdx.x;
    if (i >= n4) return;
    float4 v = ((const float4*)src)[i];
    ((uint2*)dst)[i] = make_uint2(pack_h2(v.x, v.y), pack_h2(v.z, v.w));
}

// transpose + convert: in[K][N] -> fp16 [N][K]
__global__ __launch_bounds__(256)
void tconv_h(const float* __restrict__ in, uint16_t* __restrict__ dst, int K, int N)
{
    __shared__ float t[32][33];
    int n0 = blockIdx.x * 32, k0 = blockIdx.y * 32;
    #pragma unroll
    for (int i = threadIdx.y; i < 32; i += 8)
        t[i][threadIdx.x] = in[(size_t)(k0 + i) * N + n0 + threadIdx.x];
    __syncthreads();
    #pragma unroll
    for (int i = threadIdx.y; i < 32; i += 8) {
        float v = t[threadIdx.x][i];
        dst[(size_t)(n0 + i) * K + k0 + threadIdx.x] = f2h(v);
    }
}

// ---------------------------------------------------------------------------
// Plain fp16 GEMM. BM=128 BN=128 BK=32, 256 thr, 8 warps (4x2), warp 32x64.
// qkv_mode: epilogue writes Qh(fp16,scaled)/Kh(fp16)/V(fp16,transposed).
// ---------------------------------------------------------------------------
#define LDW  20
#define MATW (128 * LDW)
#define STGW (2 * MATW)
#define GEMM_SMEM (3 * STGW * 4)

__global__ __launch_bounds__(256, 2)
void gemm_h(const uint16_t* __restrict__ Ah, const uint16_t* __restrict__ Bh,
            const float* __restrict__ bias, float* __restrict__ C,
            uint16_t* __restrict__ Qh, uint16_t* __restrict__ Kh,
            uint16_t* __restrict__ Vt, int qkv_mode,
            int N, int K)
{
    extern __shared__ uint32_t gsm[];

    const int tid  = threadIdx.x;
    const int lane = tid & 31;
    const int wid  = tid >> 5;
    const int wm   = wid >> 1;
    const int wn   = wid & 1;
    const int r0   = lane >> 2;
    const int c0   = lane & 3;
    const int bx   = blockIdx.x;
    const int by   = blockIdx.y;
    const int nt   = K / 32;
    const int Kw   = K >> 1;          // K in fp16-pair words

    auto prefetch = [&](int t, int s) {
        uint32_t* st = gsm + s * STGW;
        #pragma unroll
        for (int i = 0; i < 4; i++) {
            int idx = tid + i * 256;            // 0..1023
            int mat = idx >> 9;                 // 0..1
            int r2  = idx & 511;
            int row = r2 >> 2;                  // 0..127
            int ch  = r2 & 3;                   // 16B chunk (4 words)
            const uint16_t* S = mat ? Bh : Ah;
            int rowbase = mat ? bx * 128 : by * 128;
            const uint32_t* src = (const uint32_t*)S
                                  + (size_t)(rowbase + row) * Kw + t * 16 + ch * 4;
            cpa16(st + mat * MATW + row * LDW + ch * 4, src);
        }
    };

    float acc[2][8][4];
    #pragma unroll
    for (int mi = 0; mi < 2; mi++)
        #pragma unroll
        for (int ni = 0; ni < 8; ni++)
            #pragma unroll
            for (int j = 0; j < 4; j++) acc[mi][ni][j] = 0.f;

    prefetch(0, 0); CPA_COMMIT();
    prefetch(1, 1); CPA_COMMIT();

    for (int it = 0; it < nt; it++) {
        CPA_WAIT(1);
        __syncthreads();
        if (it + 2 < nt) prefetch(it + 2, (it + 2) % 3);
        CPA_COMMIT();

        const uint32_t* As = gsm + (it % 3) * STGW;
        const uint32_t* Bs = As + MATW;

        #pragma unroll
        for (int kc = 0; kc < 2; kc++) {
            const int kw = kc * 8 + c0;
            uint32_t a[2][4];
            #pragma unroll
            for (int mi = 0; mi < 2; mi++) {
                int m = wm * 32 + mi * 16 + r0;
                a[mi][0] = As[m * LDW + kw];
                a[mi][1] = As[(m + 8) * LDW + kw];
                a[mi][2] = As[m * LDW + kw + 4];
                a[mi][3] = As[(m + 8) * LDW + kw + 4];
            }
            #pragma unroll
            for (int ni = 0; ni < 8; ni++) {
                int n = wn * 64 + ni * 8 + r0;
                uint32_t b0 = Bs[n * LDW + kw];
                uint32_t b1 = Bs[n * LDW + kw + 4];
                #pragma unroll
                for (int mi = 0; mi < 2; mi++)
                    mma16h(acc[mi][ni], a[mi][0], a[mi][1], a[mi][2], a[mi][3], b0, b1);
            }
        }
    }

    if (!qkv_mode) {
        #pragma unroll
        for (int mi = 0; mi < 2; mi++) {
            int r = by * 128 + wm * 32 + mi * 16 + r0;
            #pragma unroll
            for (int ni = 0; ni < 8; ni++) {
                int cc = bx * 128 + wn * 64 + ni * 8 + c0 * 2;
                float bb0 = bias ? bias[cc] : 0.f;
                float bb1 = bias ? bias[cc + 1] : 0.f;
                *(float2*)(C + (size_t)r * N + cc) =
                    make_float2(acc[mi][ni][0] + bb0, acc[mi][ni][1] + bb1);
                *(float2*)(C + (size_t)(r + 8) * N + cc) =
                    make_float2(acc[mi][ni][2] + bb0, acc[mi][ni][3] + bb1);
            }
        }
    } else {
        const int plane = (bx * 128) / DIM;     // 0=Q 1=K 2=V (tiles never straddle)
        #pragma unroll
        for (int mi = 0; mi < 2; mi++) {
            int r = by * 128 + wm * 32 + mi * 16 + r0;
            #pragma unroll
            for (int ni = 0; ni < 8; ni++) {
                int cc = bx * 128 + wn * 64 + ni * 8 + c0 * 2;
                if (plane == 0) {
                    // Q: fp16, pre-scaled by 1/8
                    uint32_t* qw = (uint32_t*)Qh;
                    qw[((size_t)r * DIM + cc) >> 1] =
                        pack_h2(0.125f * acc[mi][ni][0], 0.125f * acc[mi][ni][1]);
                    qw[((size_t)(r + 8) * DIM + cc) >> 1] =
                        pack_h2(0.125f * acc[mi][ni][2], 0.125f * acc[mi][ni][3]);
                } else if (plane == 1) {
                    int q = cc - DIM;
                    uint32_t* kw = (uint32_t*)Kh;
                    kw[((size_t)r * DIM + q) >> 1] =
                        pack_h2(acc[mi][ni][0], acc[mi][ni][1]);
                    kw[((size_t)(r + 8) * DIM + q) >> 1] =
                        pack_h2(acc[mi][ni][2], acc[mi][ni][3]);
                } else {
                    int vc = cc - 2 * DIM;
                    int hh = vc >> 6, d = vc & 63;
                    int bb = r >> 11, n = r & 2047;
                    size_t base = ((size_t)(bb * HEADS + hh) * HDIM + d) * SEQ;
                    Vt[base + n]           = f2h(acc[mi][ni][0]);
                    Vt[base + SEQ + n]     = f2h(acc[mi][ni][1]);
                    Vt[base + n + 8]       = f2h(acc[mi][ni][2]);
                    Vt[base + SEQ + n + 8] = f2h(acc[mi][ni][3]);
                }
            }
        }
    }
}

// ---------------------------------------------------------------------------
// Flash attention, full fp16 tensor path:
//   S = Q K^T via fp16 m16n8k16 (Q pre-scaled 1/8, fp16 K tile [kv][d])
//   PV      via fp16 m16n8k16 (P packed in regs, V tile [d][kv])
// ---------------------------------------------------------------------------
#define LDKW 36
#define LDVT 36
#define K_TILE (64 * LDKW)
#define V_TILE (64 * LDVT)
#define ATTN_SMEM ((2 * (K_TILE + V_TILE)) * 4)
#define NTA (SEQ / 64)

__global__ __launch_bounds__(256, 2)
void attn_flash(const uint16_t* __restrict__ Qh, const uint16_t* __restrict__ Kh,
                const uint16_t* __restrict__ Vt, uint16_t* __restrict__ atth)
{
    extern __shared__ uint32_t smu[];
    uint32_t* Ksm = smu;                     // 2 x K tile (f16x2 words, [kv][d])
    uint32_t* Vsm = smu + 2 * K_TILE;        // 2 x V tile (f16x2 words, [d][kv])

    const int tid  = threadIdx.x;
    const int lane = tid & 31;
    const int wid  = tid >> 5;
    const int b    = blockIdx.z;
    const int h    = blockIdx.y;
    const int qbase = blockIdx.x * 128 + wid * 16;
    const int r0 = lane >> 2;
    const int c0 = lane & 3;
    const size_t vbase = (size_t)(b * HEADS + h) * HDIM * SEQ;

    auto stage_k = [&](int kt, int buf) {
        uint32_t* Kdst = Ksm + buf * K_TILE;
        #pragma unroll
        for (int i = 0; i < 2; i++) {
            int idx = tid + i * 256;         // 0..511
            int row = idx >> 3;              // 0..63
            int ch  = idx & 7;               // 8 fp16 per 16B chunk
            cpa16(Kdst + row * LDKW + ch * 4,
                  Kh + (size_t)(b * SEQ + kt * 64 + row) * DIM + h * HDIM + ch * 8);
        }
    };
    auto stage_v = [&](int kt, int buf) {
        uint32_t* Vdst = Vsm + buf * V_TILE;
        #pragma unroll
        for (int i = 0; i < 2; i++) {
            int idx = tid + i * 256;         // 0..511
            int d   = idx >> 3;              // 0..63
            int ch  = idx & 7;
            cpa16(Vdst + d * LDVT + ch * 4,
                  Vt + vbase + (size_t)d * SEQ + kt * 64 + ch * 8);
        }
    };

    stage_k(0, 0); stage_v(0, 0);
    CPA_COMMIT();

    // Q fragments: fp16 pairs (already scaled by 1/8). 4 k-chunks of 16.
    uint32_t qa[4][4];
    {
        const uint32_t* qw = (const uint32_t*)Qh
                             + ((size_t)(b * SEQ + qbase) * DIM + h * HDIM) / 2;
        #pragma unroll
        for (int ks = 0; ks < 4; ks++) {
            int w = ks * 8 + c0;
            qa[ks][0] = qw[(size_t)r0 * (DIM / 2) + w];
            qa[ks][1] = qw[(size_t)(r0 + 8) * (DIM / 2) + w];
            qa[ks][2] = qw[(size_t)r0 * (DIM / 2) + w + 4];
            qa[ks][3] = qw[(size_t)(r0 + 8) * (DIM / 2) + w + 4];
        }
    }

    float o[8][4];
    #pragma unroll
    for (int ni = 0; ni < 8; ni++)
        #pragma unroll
        for (int j = 0; j < 4; j++) o[ni][j] = 0.f;
    float m0 = -1e30f, m1 = -1e30f, l0 = 0.f, l1 = 0.f;

    CPA_WAIT(0);
    __syncthreads();

    for (int kt = 0; kt < NTA; kt++) {
        const int cur = kt & 1;
        if (kt + 1 < NTA) { stage_k(kt + 1, cur ^ 1); stage_v(kt + 1, cur ^ 1); }
        CPA_COMMIT();

        const uint32_t* Kc = Ksm + cur * K_TILE;
        const uint32_t* Vc = Vsm + cur * V_TILE;

        // S = Q K^T : fp16 m16n8k16, 4 k-chunks x 8 kv-groups
        float s[8][4];
        #pragma unroll
        for (int ni = 0; ni < 8; ni++)
            #pragma unroll
            for (int j = 0; j < 4; j++) s[ni][j] = 0.f;

        #pragma unroll
        for (int ks = 0; ks < 4; ks++) {
            int w = ks * 8 + c0;
            #pragma unroll
            for (int ni = 0; ni < 8; ni++) {
                int kvr = ni * 8 + r0;
                mma16h(s[ni], qa[ks][0], qa[ks][1], qa[ks][2], qa[ks][3],
                       Kc[kvr * LDKW + w], Kc[kvr * LDKW + w + 4]);
            }
        }

        // online softmax (p overwrites s in-place)
        float tm0 = -1e30f, tm1 = -1e30f;
        #pragma unroll
        for (int ni = 0; ni < 8; ni++) {
            tm0 = fmaxf(tm0, fmaxf(s[ni][0], s[ni][1]));
            tm1 = fmaxf(tm1, fmaxf(s[ni][2], s[ni][3]));
        }
        tm0 = fmaxf(tm0, __shfl_xor_sync(0xffffffffu, tm0, 1));
        tm0 = fmaxf(tm0, __shfl_xor_sync(0xffffffffu, tm0, 2));
        tm1 = fmaxf(tm1, __shfl_xor_sync(0xffffffffu, tm1, 1));
        tm1 = fmaxf(tm1, __shfl_xor_sync(0xffffffffu, tm1, 2));

        float nm0 = fmaxf(m0, tm0), nm1 = fmaxf(m1, tm1);
        float cor0 = __expf(m0 - nm0), cor1 = __expf(m1 - nm1);
        m0 = nm0; m1 = nm1;
        l0 *= cor0; l1 *= cor1;
        #pragma unroll
        for (int ni = 0; ni < 8; ni++) {
            o[ni][0] *= cor0; o[ni][1] *= cor0;
            o[ni][2] *= cor1; o[ni][3] *= cor1;
        }
        #pragma unroll
        for (int ni = 0; ni < 8; ni++) {
            s[ni][0] = __expf(s[ni][0] - nm0);
            s[ni][1] = __expf(s[ni][1] - nm0);
            s[ni][2] = __expf(s[ni][2] - nm1);
            s[ni][3] = __expf(s[ni][3] - nm1);
            l0 += s[ni][0] + s[ni][1];
            l1 += s[ni][2] + s[ni][3];
        }

        // O += P V : fp16 m16n8k16, P packed in registers
        #pragma unroll
        for (int j = 0; j < 4; j++) {
            uint32_t a0 = pack_h2(s[2 * j][0],     s[2 * j][1]);
            uint32_t a1 = pack_h2(s[2 * j][2],     s[2 * j][3]);
            uint32_t a2 = pack_h2(s[2 * j + 1][0], s[2 * j + 1][1]);
            uint32_t a3 = pack_h2(s[2 * j + 1][2], s[2 * j + 1][3]);
            #pragma unroll
            for (int nd = 0; nd < 8; nd++) {
                const uint32_t* vr = Vc + (nd * 8 + r0) * LDVT + 8 * j + c0;
                mma16h(o[nd], a0, a1, a2, a3, vr[0], vr[4]);
            }
        }

        if (kt + 1 < NTA) {
            CPA_WAIT(0);
            __syncthreads();
        }
    }

    l0 += __shfl_xor_sync(0xffffffffu, l0, 1);
    l0 += __shfl_xor_sync(0xffffffffu, l0, 2);
    l1 += __shfl_xor_sync(0xffffffffu, l1, 1);
    l1 += __shfl_xor_sync(0xffffffffu, l1, 2);
    float inv0 = 1.f / l0, inv1 = 1.f / l1;

    // epilogue: fp16 att for proj GEMM
    size_t rbase = (size_t)(b * SEQ + qbase) * DIM + h * HDIM;
    #pragma unroll
    for (int ni = 0; ni < 8; ni++) {
        int d = ni * 8 + c0 * 2;
        size_t i0 = rbase + (size_t)r0 * DIM + d;
        size_t i1 = rbase + (size_t)(r0 + 8) * DIM + d;
        *(uint32_t*)&atth[i0] = pack_h2(o[ni][0] * inv0, o[ni][1] * inv0);
        *(uint32_t*)&atth[i1] = pack_h2(o[ni][2] * inv1, o[ni][3] * inv1);
    }
}

// ---------------------------------------------------------------------------
extern "C" void kernel_launch(void* const* d_in, const int* in_sizes, int n_in,
                              void* d_out, int out_size)
{
    const float* x      = (const float*)d_in[0];
    const float* w_qkv  = (const float*)d_in[1];
    const float* w_proj = (const float*)d_in[2];
    const float* b_proj = (const float*)d_in[3];
    float* out = (float*)d_out;

    uint16_t *qh, *kh, *vt, *xh, *wqh, *wph, *ath;
    cudaGetSymbolAddress((void**)&qh,  g_qh);
    cudaGetSymbolAddress((void**)&kh,  g_kh);
    cudaGetSymbolAddress((void**)&vt,  g_vT);
    cudaGetSymbolAddress((void**)&xh,  g_xh);
    cudaGetSymbolAddress((void**)&wqh, g_wqkvh);
    cudaGetSymbolAddress((void**)&wph, g_wprojh);
    cudaGetSymbolAddress((void**)&ath, g_atth);

    cudaFuncSetAttribute(gemm_h, cudaFuncAttributeMaxDynamicSharedMemorySize, GEMM_SMEM);
    cudaFuncSetAttribute(attn_flash, cudaFuncAttributeMaxDynamicSharedMemorySize, ATTN_SMEM);

    // 0) convert inputs to fp16 (weights transposed to [N][K])
    conv_h<<<(M_TOT * DIM / 4 + 255) / 256, 256>>>(x, xh, M_TOT * DIM / 4);
    tconv_h<<<dim3(QKV_N / 32, DIM / 32), dim3(32, 8)>>>(w_qkv, wqh, DIM, QKV_N);
    tconv_h<<<dim3(DIM / 32, DIM / 32), dim3(32, 8)>>>(w_proj, wph, DIM, DIM);

    // 1) qkv GEMM -> Q/K (fp16) + transposed V (fp16)
    gemm_h<<<dim3(QKV_N / 128, M_TOT / 128), 256, GEMM_SMEM>>>(
        xh, wqh, nullptr, nullptr, qh, kh, vt, 1, QKV_N, DIM);
    // 2) attention -> att (fp16)
    attn_flash<<<dim3(SEQ / 128, HEADS, BATCH), 256, ATTN_SMEM>>>(qh, kh, vt, ath);
    // 3) out = att @ w_proj + b
    gemm_h<<<dim3(DIM / 128, M_TOT / 128), 256, GEMM_SMEM>>>(
        ath, wph, b_proj, out, nullptr, nullptr, nullptr, 0, DIM, DIM);
}